// round 11
// baseline (speedup 1.0000x reference)
#include <cuda_runtime.h>
#include <cuda_fp16.h>

#define N_NODES 50000
#define N_EDGES 800000
#define ET (N_EDGES + N_NODES)        // edges + self loops
#define ESRC_SZ (ET + 3 * N_NODES)    // padded CSR capacity
#define IN_DIM 128
#define D1 32
#define D2 64
#define SLOPE 0.2f

#define SCAT_BLKS (((ET + 3) / 4 + 255) / 256)          // 831
#define PAD_BLKS  ((N_NODES + 255) / 256)               // 196

// ---------------- scratch ----------------
__device__ __align__(16) __half  g_h1h[N_NODES * D1];    // x@W1, fp16
__device__ __align__(16) float g_s1[N_NODES * 2];
__device__ __align__(16) float g_d1[N_NODES * 2];
__device__ __align__(16) float g_h1e[N_NODES * D1];      // elu(gat1 out), fp32
__device__ __align__(16) __half2 g_h2h[N_NODES * 32];    // layer2 feats fp16
__device__ float g_s2[N_NODES];
__device__ float g_d2[N_NODES];
__device__ int   g_deg[N_NODES];          // zero at load; re-zeroed in k_scan
__device__ int   g_off[N_NODES];
__device__ int   g_dend[N_NODES];         // off + true degree
__device__ int   g_cur[N_NODES];
__device__ __align__(16) int   g_esrc[ESRC_SZ + 8];      // CSR src per slot
__device__ __align__(16) int   g_edst[ESRC_SZ + 8];      // CSR dst per slot (-1 = pad)
__device__ __align__(16) float g_w1a[ESRC_SZ + 8];       // layer1 weight, head 0
__device__ __align__(16) float g_w1b[ESRC_SZ + 8];       // layer1 weight, head 1
__device__ __align__(16) float g_w2[ESRC_SZ + 8];        // layer2 weight

__device__ __forceinline__ int detect64(const int* ei32) {
    // int64 LE with values < 2^31 => odd 32-bit words are 0.
    return ((ei32[1] | ei32[3] | ei32[5] | ei32[7]) == 0) ? 1 : 0;
}

// ---------------- gemm1 + sd1 (8 threads / node quad, 4 cols x 4 nodes) -------
__global__ void __launch_bounds__(256) k_gemm1(
        const float* __restrict__ x, const float* __restrict__ W1,
        const float* __restrict__ a_src, const float* __restrict__ a_dst) {
    __shared__ float4 Ws4[IN_DIM * (D1 / 4)];   // 16 KB
    for (int i = threadIdx.x; i < IN_DIM * (D1 / 4); i += blockDim.x)
        Ws4[i] = ((const float4*)W1)[i];
    __syncthreads();

    int tid  = blockIdx.x * blockDim.x + threadIdx.x;
    int quad = tid >> 3;
    int sub  = tid & 7;
    if (quad >= N_NODES / 4) return;
    int n0 = quad * 4;

    const float4* x0p = (const float4*)(x + (n0 + 0) * IN_DIM);
    const float4* x1p = (const float4*)(x + (n0 + 1) * IN_DIM);
    const float4* x2p = (const float4*)(x + (n0 + 2) * IN_DIM);
    const float4* x3p = (const float4*)(x + (n0 + 3) * IN_DIM);
    float4 a0 = make_float4(0.f, 0.f, 0.f, 0.f);
    float4 a1 = a0, a2 = a0, a3 = a0;
#pragma unroll 2
    for (int k4 = 0; k4 < 32; k4++) {
        float4 w0 = Ws4[(k4 * 4 + 0) * 8 + sub];
        float4 w1 = Ws4[(k4 * 4 + 1) * 8 + sub];
        float4 w2 = Ws4[(k4 * 4 + 2) * 8 + sub];
        float4 w3 = Ws4[(k4 * 4 + 3) * 8 + sub];
        float4 xv;
        xv = x0p[k4];
        a0.x += xv.x * w0.x + xv.y * w1.x + xv.z * w2.x + xv.w * w3.x;
        a0.y += xv.x * w0.y + xv.y * w1.y + xv.z * w2.y + xv.w * w3.y;
        a0.z += xv.x * w0.z + xv.y * w1.z + xv.z * w2.z + xv.w * w3.z;
        a0.w += xv.x * w0.w + xv.y * w1.w + xv.z * w2.w + xv.w * w3.w;
        xv = x1p[k4];
        a1.x += xv.x * w0.x + xv.y * w1.x + xv.z * w2.x + xv.w * w3.x;
        a1.y += xv.x * w0.y + xv.y * w1.y + xv.z * w2.y + xv.w * w3.y;
        a1.z += xv.x * w0.z + xv.y * w1.z + xv.z * w2.z + xv.w * w3.z;
        a1.w += xv.x * w0.w + xv.y * w1.w + xv.z * w2.w + xv.w * w3.w;
        xv = x2p[k4];
        a2.x += xv.x * w0.x + xv.y * w1.x + xv.z * w2.x + xv.w * w3.x;
        a2.y += xv.x * w0.y + xv.y * w1.y + xv.z * w2.y + xv.w * w3.y;
        a2.z += xv.x * w0.z + xv.y * w1.z + xv.z * w2.z + xv.w * w3.z;
        a2.w += xv.x * w0.w + xv.y * w1.w + xv.z * w2.w + xv.w * w3.w;
        xv = x3p[k4];
        a3.x += xv.x * w0.x + xv.y * w1.x + xv.z * w2.x + xv.w * w3.x;
        a3.y += xv.x * w0.y + xv.y * w1.y + xv.z * w2.y + xv.w * w3.y;
        a3.z += xv.x * w0.z + xv.y * w1.z + xv.z * w2.z + xv.w * w3.z;
        a3.w += xv.x * w0.w + xv.y * w1.w + xv.z * w2.w + xv.w * w3.w;
    }
    __half2* h1p = (__half2*)g_h1h;
    h1p[(n0 + 0) * 16 + sub * 2]     = __floats2half2_rn(a0.x, a0.y);
    h1p[(n0 + 0) * 16 + sub * 2 + 1] = __floats2half2_rn(a0.z, a0.w);
    h1p[(n0 + 1) * 16 + sub * 2]     = __floats2half2_rn(a1.x, a1.y);
    h1p[(n0 + 1) * 16 + sub * 2 + 1] = __floats2half2_rn(a1.z, a1.w);
    h1p[(n0 + 2) * 16 + sub * 2]     = __floats2half2_rn(a2.x, a2.y);
    h1p[(n0 + 2) * 16 + sub * 2 + 1] = __floats2half2_rn(a2.z, a2.w);
    h1p[(n0 + 3) * 16 + sub * 2]     = __floats2half2_rn(a3.x, a3.y);
    h1p[(n0 + 3) * 16 + sub * 2 + 1] = __floats2half2_rn(a3.z, a3.w);

    float4 as = ((const float4*)a_src)[sub];
    float4 ad = ((const float4*)a_dst)[sub];
    float s0 = a0.x * as.x + a0.y * as.y + a0.z * as.z + a0.w * as.w;
    float d0 = a0.x * ad.x + a0.y * ad.y + a0.z * ad.z + a0.w * ad.w;
    float s1 = a1.x * as.x + a1.y * as.y + a1.z * as.z + a1.w * as.w;
    float d1 = a1.x * ad.x + a1.y * ad.y + a1.z * ad.z + a1.w * ad.w;
    float s2 = a2.x * as.x + a2.y * as.y + a2.z * as.z + a2.w * as.w;
    float d2 = a2.x * ad.x + a2.y * ad.y + a2.z * ad.z + a2.w * ad.w;
    float s3 = a3.x * as.x + a3.y * as.y + a3.z * as.z + a3.w * as.w;
    float d3 = a3.x * ad.x + a3.y * ad.y + a3.z * ad.z + a3.w * ad.w;
#pragma unroll
    for (int o = 2; o; o >>= 1) {
        s0 += __shfl_down_sync(0xffffffffu, s0, o, 4);
        d0 += __shfl_down_sync(0xffffffffu, d0, o, 4);
        s1 += __shfl_down_sync(0xffffffffu, s1, o, 4);
        d1 += __shfl_down_sync(0xffffffffu, d1, o, 4);
        s2 += __shfl_down_sync(0xffffffffu, s2, o, 4);
        d2 += __shfl_down_sync(0xffffffffu, d2, o, 4);
        s3 += __shfl_down_sync(0xffffffffu, s3, o, 4);
        d3 += __shfl_down_sync(0xffffffffu, d3, o, 4);
    }
    if ((sub & 3) == 0) {
        int head = sub >> 2;
        g_s1[(n0 + 0) * 2 + head] = s0;  g_d1[(n0 + 0) * 2 + head] = d0;
        g_s1[(n0 + 1) * 2 + head] = s1;  g_d1[(n0 + 1) * 2 + head] = d1;
        g_s1[(n0 + 2) * 2 + head] = s2;  g_d1[(n0 + 2) * 2 + head] = d2;
        g_s1[(n0 + 3) * 2 + head] = s3;  g_d1[(n0 + 3) * 2 + head] = d3;
    }
}

// ---------------- histogram of dst degrees (4 edges / thread) -----------------
__global__ void k_hist(const int* __restrict__ ei32) {
    int base = (blockIdx.x * blockDim.x + threadIdx.x) * 4;
    int is64 = detect64(ei32);
#pragma unroll
    for (int k = 0; k < 4; k++) {
        int i = base + k;
        if (i >= ET) return;
        int dst;
        if (i < N_EDGES) dst = is64 ? ei32[2 * (N_EDGES + i)] : ei32[N_EDGES + i];
        else             dst = i - N_EDGES;
        atomicAdd(&g_deg[dst], 1);
    }
}

// ---- scan: padded exclusive scan -> off/cur/dend; re-zeroes deg ---------------
__global__ void k_scan() {
    __shared__ int ps[1024];
    const int CH = (N_NODES + 1023) / 1024;   // 49
    int t = threadIdx.x;
    int b = t * CH;
    int e = min(b + CH, N_NODES);
    int s = 0;
#pragma unroll 4
    for (int i = b; i < e; i++) s += (g_deg[i] + 3) & ~3;
    ps[t] = s;
    __syncthreads();
    for (int off = 1; off < 1024; off <<= 1) {
        int v = (t >= off) ? ps[t - off] : 0;
        __syncthreads();
        ps[t] += v;
        __syncthreads();
    }
    int run = (t == 0) ? 0 : ps[t - 1];
    for (int i = b; i < e; i++) {
        int d = g_deg[i];
        g_off[i]  = run;
        g_cur[i]  = run;
        g_dend[i] = run + d;
        g_deg[i]  = 0;
        run += (d + 3) & ~3;
    }
}

// ---- scatter: CSR fill + layer1 edge weights  |  pad fill --------------------
__global__ void k_scatterW(const int* __restrict__ ei32) {
    if (blockIdx.x >= SCAT_BLKS) {
        int node = (blockIdx.x - SCAT_BLKS) * 256 + threadIdx.x;
        if (node >= N_NODES) return;
        int dend = g_dend[node];
        int pend = g_off[node] + ((dend - g_off[node] + 3) & ~3);
        for (int p = dend; p < pend; p++) {
            g_esrc[p] = 0;
            g_edst[p] = -1;
            g_w1a[p] = 0.f;
            g_w1b[p] = 0.f;
        }
        return;
    }
    int base = (blockIdx.x * 256 + threadIdx.x) * 4;
    int is64 = detect64(ei32);
#pragma unroll
    for (int k = 0; k < 4; k++) {
        int i = base + k;
        if (i >= ET) return;
        int src, dst;
        if (i < N_EDGES) {
            if (is64) { src = ei32[2 * i]; dst = ei32[2 * (N_EDGES + i)]; }
            else      { src = ei32[i];     dst = ei32[N_EDGES + i]; }
        } else {
            src = dst = i - N_EDGES;
        }
        int pos = atomicAdd(&g_cur[dst], 1);
        g_esrc[pos] = src;
        g_edst[pos] = dst;
        float2 sv = ((const float2*)g_s1)[src];
        float2 dv = ((const float2*)g_d1)[dst];
        float l0 = sv.x + dv.x;
        float l1 = sv.y + dv.y;
        l0 = (l0 >= 0.f) ? l0 : SLOPE * l0;
        l1 = (l1 >= 0.f) ? l1 : SLOPE * l1;
        g_w1a[pos] = __expf(l0);
        g_w1b[pos] = __expf(l1);
    }
}

// ---- gather layer 1: pure weighted gather + elu (warp / node) ----------------
__global__ void k_gather1(const float* __restrict__ bias1) {
    int node = blockIdx.x * (blockDim.x >> 5) + (threadIdx.x >> 5);
    int lane = threadIdx.x & 31;
    if (node >= N_NODES) return;
    int beg = g_off[node];
    int n4  = (g_dend[node] - beg + 3) >> 2;
    int head = lane >> 4;
    const int4*   ep = (const int4*)(g_esrc + beg);
    const float4* wp = (const float4*)((head ? g_w1b : g_w1a) + beg);
    float acc = 0.f, z = 0.f;
#pragma unroll 2
    for (int it = 0; it < n4; it++) {
        int4   sv = ep[it];
        float4 wv = wp[it];
        float h0 = __half2float(g_h1h[sv.x * D1 + lane]);
        float h1 = __half2float(g_h1h[sv.y * D1 + lane]);
        float h2 = __half2float(g_h1h[sv.z * D1 + lane]);
        float h3 = __half2float(g_h1h[sv.w * D1 + lane]);
        acc += h0 * wv.x + h1 * wv.y + h2 * wv.z + h3 * wv.w;
        z   += (wv.x + wv.y) + (wv.z + wv.w);
    }
    float v = acc / (z + 1e-16f) + bias1[lane];
    g_h1e[node * D1 + lane] = (v > 0.f) ? v : expm1f(v);
}

// ---- gemm2 + sd2 fused (16 threads / node pair) ------------------------------
__global__ void k_gemm2(const float* __restrict__ W2,
                        const float* __restrict__ a_src, const float* __restrict__ a_dst) {
    __shared__ float4 Ws4[D1 * (D2 / 4)];   // 8 KB
    for (int i = threadIdx.x; i < D1 * (D2 / 4); i += blockDim.x)
        Ws4[i] = ((const float4*)W2)[i];
    __syncthreads();

    int tid  = blockIdx.x * blockDim.x + threadIdx.x;
    int pair = tid >> 4;
    int sub  = tid & 15;
    if (pair >= N_NODES / 2) return;
    int n0 = pair * 2, n1 = n0 + 1;

    const float4* hr0 = (const float4*)(g_h1e + n0 * D1);
    const float4* hr1 = (const float4*)(g_h1e + n1 * D1);
    float4 acc0 = make_float4(0.f, 0.f, 0.f, 0.f);
    float4 acc1 = make_float4(0.f, 0.f, 0.f, 0.f);
#pragma unroll
    for (int k4 = 0; k4 < 8; k4++) {
        float4 xa = hr0[k4];
        float4 xb = hr1[k4];
        float4 w0 = Ws4[(k4 * 4 + 0) * 16 + sub];
        float4 w1 = Ws4[(k4 * 4 + 1) * 16 + sub];
        float4 w2 = Ws4[(k4 * 4 + 2) * 16 + sub];
        float4 w3 = Ws4[(k4 * 4 + 3) * 16 + sub];
        acc0.x += xa.x * w0.x + xa.y * w1.x + xa.z * w2.x + xa.w * w3.x;
        acc0.y += xa.x * w0.y + xa.y * w1.y + xa.z * w2.y + xa.w * w3.y;
        acc0.z += xa.x * w0.z + xa.y * w1.z + xa.z * w2.z + xa.w * w3.z;
        acc0.w += xa.x * w0.w + xa.y * w1.w + xa.z * w2.w + xa.w * w3.w;
        acc1.x += xb.x * w0.x + xb.y * w1.x + xb.z * w2.x + xb.w * w3.x;
        acc1.y += xb.x * w0.y + xb.y * w1.y + xb.z * w2.y + xb.w * w3.y;
        acc1.z += xb.x * w0.z + xb.y * w1.z + xb.z * w2.z + xb.w * w3.z;
        acc1.w += xb.x * w0.w + xb.y * w1.w + xb.z * w2.w + xb.w * w3.w;
    }
    g_h2h[n0 * 32 + sub * 2]     = __floats2half2_rn(acc0.x, acc0.y);
    g_h2h[n0 * 32 + sub * 2 + 1] = __floats2half2_rn(acc0.z, acc0.w);
    g_h2h[n1 * 32 + sub * 2]     = __floats2half2_rn(acc1.x, acc1.y);
    g_h2h[n1 * 32 + sub * 2 + 1] = __floats2half2_rn(acc1.z, acc1.w);

    float4 as = ((const float4*)a_src)[sub];
    float4 ad = ((const float4*)a_dst)[sub];
    float s0 = acc0.x * as.x + acc0.y * as.y + acc0.z * as.z + acc0.w * as.w;
    float d0 = acc0.x * ad.x + acc0.y * ad.y + acc0.z * ad.z + acc0.w * ad.w;
    float s1 = acc1.x * as.x + acc1.y * as.y + acc1.z * as.z + acc1.w * as.w;
    float d1 = acc1.x * ad.x + acc1.y * ad.y + acc1.z * ad.z + acc1.w * ad.w;
#pragma unroll
    for (int o = 8; o; o >>= 1) {
        s0 += __shfl_down_sync(0xffffffffu, s0, o, 16);
        d0 += __shfl_down_sync(0xffffffffu, d0, o, 16);
        s1 += __shfl_down_sync(0xffffffffu, s1, o, 16);
        d1 += __shfl_down_sync(0xffffffffu, d1, o, 16);
    }
    if (sub == 0) {
        g_s2[n0] = s0;
        g_d2[n0] = d0;
        g_s2[n1] = s1;
        g_d2[n1] = d1;
    }
}

// ---- layer2 edge weights (slot-parallel over CSR) -----------------------------
__global__ void k_w2() {
    int p = blockIdx.x * blockDim.x + threadIdx.x;
    if (p >= ESRC_SZ) return;
    int dst = g_edst[p];
    float w = 0.f;
    if (dst >= 0) {
        float l = g_s2[g_esrc[p]] + g_d2[dst];
        l = (l >= 0.f) ? l : SLOPE * l;
        w = __expf(l);
    }
    g_w2[p] = w;
}

// ---- gather layer 2: pure weighted gather (warp / node, half2 lanes) ---------
__global__ void k_gather2(const float* __restrict__ bias2, float* __restrict__ out) {
    int node = blockIdx.x * (blockDim.x >> 5) + (threadIdx.x >> 5);
    int lane = threadIdx.x & 31;
    if (node >= N_NODES) return;
    int beg = g_off[node];
    int n4  = (g_dend[node] - beg + 3) >> 2;
    const int4*   ep = (const int4*)(g_esrc + beg);
    const float4* wp = (const float4*)(g_w2 + beg);
    float ax = 0.f, ay = 0.f, z = 0.f;
#pragma unroll 2
    for (int it = 0; it < n4; it++) {
        int4   sv = ep[it];
        float4 wv = wp[it];
        float2 h0 = __half22float2(g_h2h[sv.x * 32 + lane]);
        float2 h1 = __half22float2(g_h2h[sv.y * 32 + lane]);
        float2 h2 = __half22float2(g_h2h[sv.z * 32 + lane]);
        float2 h3 = __half22float2(g_h2h[sv.w * 32 + lane]);
        ax += h0.x * wv.x + h1.x * wv.y + h2.x * wv.z + h3.x * wv.w;
        ay += h0.y * wv.x + h1.y * wv.y + h2.y * wv.z + h3.y * wv.w;
        z  += (wv.x + wv.y) + (wv.z + wv.w);
    }
    float inv = 1.f / (z + 1e-16f);
    float2 o2;
    o2.x = ax * inv + bias2[lane * 2];
    o2.y = ay * inv + bias2[lane * 2 + 1];
    *(float2*)(out + node * D2 + lane * 2) = o2;
}

extern "C" void kernel_launch(void* const* d_in, const int* in_sizes, int n_in,
                              void* d_out, int out_size) {
    const float* x     = (const float*)d_in[0];
    const int*   ei32  = (const int*)d_in[1];
    const float* W1    = (const float*)d_in[2];
    const float* asrc1 = (const float*)d_in[3];
    const float* adst1 = (const float*)d_in[4];
    const float* bias1 = (const float*)d_in[5];
    const float* W2    = (const float*)d_in[6];
    const float* asrc2 = (const float*)d_in[7];
    const float* adst2 = (const float*)d_in[8];
    const float* bias2 = (const float*)d_in[9];
    float* out = (float*)d_out;

    const int T = 256;

    static cudaStream_t s2 = nullptr;
    static cudaEvent_t  evF = nullptr, evJ = nullptr;
    if (!s2) {
        cudaStreamCreateWithFlags(&s2, cudaStreamNonBlocking);
        cudaEventCreateWithFlags(&evF, cudaEventDisableTiming);
        cudaEventCreateWithFlags(&evJ, cudaEventDisableTiming);
    }

    // fork: gemm1 (inputs only) overlaps with CSR histogram + scan
    cudaEventRecord(evF, 0);
    cudaStreamWaitEvent(s2, evF, 0);
    k_gemm1<<<((N_NODES / 4) * 8 + T - 1) / T, T, 0, s2>>>(x, W1, asrc1, adst1); // 1
    cudaEventRecord(evJ, s2);

    k_hist<<<((ET + 3) / 4 + T - 1) / T, T>>>(ei32);                             // 2
    k_scan<<<1, 1024>>>();                                                       // 3

    // join: scatterW needs s1/d1 (gemm1) + offsets (scan)
    cudaStreamWaitEvent(0, evJ, 0);
    k_scatterW<<<SCAT_BLKS + PAD_BLKS, T>>>(ei32);                               // 4 <- profiled
    k_gather1<<<(N_NODES + 7) / 8, T>>>(bias1);                                  // 5
    k_gemm2<<<((N_NODES / 2) * 16 + T - 1) / T, T>>>(W2, asrc2, adst2);          // 6
    k_w2<<<(ESRC_SZ + T - 1) / T, T>>>();                                        // 7
    k_gather2<<<(N_NODES + 7) / 8, T>>>(bias2, out);                             // 8
}

// round 12
// speedup vs baseline: 1.0822x; 1.0822x over previous
#include <cuda_runtime.h>
#include <cuda_fp16.h>

#define N_NODES 50000
#define N_EDGES 800000
#define ET (N_EDGES + N_NODES)        // edges + self loops
#define ESRC_SZ (ET + 3 * N_NODES)    // padded CSR capacity
#define IN_DIM 128
#define D1 32
#define D2 64
#define SLOPE 0.2f

#define GEMM1_BLKS ((N_NODES / 4 * 8 + 255) / 256)      // 391
#define HIST_BLKS  (((ET + 3) / 4 + 255) / 256)         // 831
#define PAD_BLKS   ((N_NODES + 255) / 256)              // 196

// ---------------- scratch ----------------
__device__ __align__(16) __half  g_h1h[N_NODES * D1];    // x@W1, fp16
__device__ __align__(16) float g_s1[N_NODES * 2];
__device__ __align__(16) float g_d1[N_NODES * 2];
__device__ __align__(16) float g_h1e[N_NODES * D1];      // elu(gat1 out), fp32
__device__ __align__(16) __half2 g_h2h[N_NODES * 32];    // layer2 feats fp16
__device__ float g_s2[N_NODES];
__device__ float g_d2[N_NODES];
__device__ int   g_deg[N_NODES];          // zero at load; re-zeroed in k_scan
__device__ int   g_off[N_NODES];
__device__ int   g_dend[N_NODES];         // off + true degree
__device__ int   g_cur[N_NODES];
__device__ __align__(16) int4  g_slot[ESRC_SZ + 8];      // AoS: {src, w1a, w1b, dst}
__device__ __align__(16) float g_w2[ESRC_SZ + 8];        // layer2 weight (SoA)

__device__ __forceinline__ int detect64(const int* ei32) {
    // int64 LE with values < 2^31 => odd 32-bit words are 0.
    return ((ei32[1] | ei32[3] | ei32[5] | ei32[7]) == 0) ? 1 : 0;
}

// ---------------- fused gemm1 + sd1  |  degree histogram ----------------------
__global__ void __launch_bounds__(256) k_gemm1hist(
        const float* __restrict__ x, const float* __restrict__ W1,
        const float* __restrict__ a_src, const float* __restrict__ a_dst,
        const int* __restrict__ ei32) {
    if (blockIdx.x >= GEMM1_BLKS) {
        int hb = blockIdx.x - GEMM1_BLKS;
        int base = (hb * 256 + threadIdx.x) * 4;
        int is64 = detect64(ei32);
#pragma unroll
        for (int k = 0; k < 4; k++) {
            int i = base + k;
            if (i >= ET) return;
            int dst;
            if (i < N_EDGES) dst = is64 ? ei32[2 * (N_EDGES + i)] : ei32[N_EDGES + i];
            else             dst = i - N_EDGES;
            atomicAdd(&g_deg[dst], 1);
        }
        return;
    }

    __shared__ float4 Ws4[IN_DIM * (D1 / 4)];   // 16 KB
    for (int i = threadIdx.x; i < IN_DIM * (D1 / 4); i += blockDim.x)
        Ws4[i] = ((const float4*)W1)[i];
    __syncthreads();

    int tid  = blockIdx.x * blockDim.x + threadIdx.x;
    int quad = tid >> 3;
    int sub  = tid & 7;
    if (quad >= N_NODES / 4) return;
    int n0 = quad * 4;

    const float4* x0p = (const float4*)(x + (n0 + 0) * IN_DIM);
    const float4* x1p = (const float4*)(x + (n0 + 1) * IN_DIM);
    const float4* x2p = (const float4*)(x + (n0 + 2) * IN_DIM);
    const float4* x3p = (const float4*)(x + (n0 + 3) * IN_DIM);
    float4 a0 = make_float4(0.f, 0.f, 0.f, 0.f);
    float4 a1 = a0, a2 = a0, a3 = a0;
#pragma unroll 2
    for (int k4 = 0; k4 < 32; k4++) {
        float4 w0 = Ws4[(k4 * 4 + 0) * 8 + sub];
        float4 w1 = Ws4[(k4 * 4 + 1) * 8 + sub];
        float4 w2 = Ws4[(k4 * 4 + 2) * 8 + sub];
        float4 w3 = Ws4[(k4 * 4 + 3) * 8 + sub];
        float4 xv;
        xv = x0p[k4];
        a0.x += xv.x * w0.x + xv.y * w1.x + xv.z * w2.x + xv.w * w3.x;
        a0.y += xv.x * w0.y + xv.y * w1.y + xv.z * w2.y + xv.w * w3.y;
        a0.z += xv.x * w0.z + xv.y * w1.z + xv.z * w2.z + xv.w * w3.z;
        a0.w += xv.x * w0.w + xv.y * w1.w + xv.z * w2.w + xv.w * w3.w;
        xv = x1p[k4];
        a1.x += xv.x * w0.x + xv.y * w1.x + xv.z * w2.x + xv.w * w3.x;
        a1.y += xv.x * w0.y + xv.y * w1.y + xv.z * w2.y + xv.w * w3.y;
        a1.z += xv.x * w0.z + xv.y * w1.z + xv.z * w2.z + xv.w * w3.z;
        a1.w += xv.x * w0.w + xv.y * w1.w + xv.z * w2.w + xv.w * w3.w;
        xv = x2p[k4];
        a2.x += xv.x * w0.x + xv.y * w1.x + xv.z * w2.x + xv.w * w3.x;
        a2.y += xv.x * w0.y + xv.y * w1.y + xv.z * w2.y + xv.w * w3.y;
        a2.z += xv.x * w0.z + xv.y * w1.z + xv.z * w2.z + xv.w * w3.z;
        a2.w += xv.x * w0.w + xv.y * w1.w + xv.z * w2.w + xv.w * w3.w;
        xv = x3p[k4];
        a3.x += xv.x * w0.x + xv.y * w1.x + xv.z * w2.x + xv.w * w3.x;
        a3.y += xv.x * w0.y + xv.y * w1.y + xv.z * w2.y + xv.w * w3.y;
        a3.z += xv.x * w0.z + xv.y * w1.z + xv.z * w2.z + xv.w * w3.z;
        a3.w += xv.x * w0.w + xv.y * w1.w + xv.z * w2.w + xv.w * w3.w;
    }
    __half2* h1p = (__half2*)g_h1h;
    h1p[(n0 + 0) * 16 + sub * 2]     = __floats2half2_rn(a0.x, a0.y);
    h1p[(n0 + 0) * 16 + sub * 2 + 1] = __floats2half2_rn(a0.z, a0.w);
    h1p[(n0 + 1) * 16 + sub * 2]     = __floats2half2_rn(a1.x, a1.y);
    h1p[(n0 + 1) * 16 + sub * 2 + 1] = __floats2half2_rn(a1.z, a1.w);
    h1p[(n0 + 2) * 16 + sub * 2]     = __floats2half2_rn(a2.x, a2.y);
    h1p[(n0 + 2) * 16 + sub * 2 + 1] = __floats2half2_rn(a2.z, a2.w);
    h1p[(n0 + 3) * 16 + sub * 2]     = __floats2half2_rn(a3.x, a3.y);
    h1p[(n0 + 3) * 16 + sub * 2 + 1] = __floats2half2_rn(a3.z, a3.w);

    float4 as = ((const float4*)a_src)[sub];
    float4 ad = ((const float4*)a_dst)[sub];
    float s0 = a0.x * as.x + a0.y * as.y + a0.z * as.z + a0.w * as.w;
    float d0 = a0.x * ad.x + a0.y * ad.y + a0.z * ad.z + a0.w * ad.w;
    float s1 = a1.x * as.x + a1.y * as.y + a1.z * as.z + a1.w * as.w;
    float d1 = a1.x * ad.x + a1.y * ad.y + a1.z * ad.z + a1.w * ad.w;
    float s2 = a2.x * as.x + a2.y * as.y + a2.z * as.z + a2.w * as.w;
    float d2 = a2.x * ad.x + a2.y * ad.y + a2.z * ad.z + a2.w * ad.w;
    float s3 = a3.x * as.x + a3.y * as.y + a3.z * as.z + a3.w * as.w;
    float d3 = a3.x * ad.x + a3.y * ad.y + a3.z * ad.z + a3.w * ad.w;
#pragma unroll
    for (int o = 2; o; o >>= 1) {
        s0 += __shfl_down_sync(0xffffffffu, s0, o, 4);
        d0 += __shfl_down_sync(0xffffffffu, d0, o, 4);
        s1 += __shfl_down_sync(0xffffffffu, s1, o, 4);
        d1 += __shfl_down_sync(0xffffffffu, d1, o, 4);
        s2 += __shfl_down_sync(0xffffffffu, s2, o, 4);
        d2 += __shfl_down_sync(0xffffffffu, d2, o, 4);
        s3 += __shfl_down_sync(0xffffffffu, s3, o, 4);
        d3 += __shfl_down_sync(0xffffffffu, d3, o, 4);
    }
    if ((sub & 3) == 0) {
        int head = sub >> 2;
        g_s1[(n0 + 0) * 2 + head] = s0;  g_d1[(n0 + 0) * 2 + head] = d0;
        g_s1[(n0 + 1) * 2 + head] = s1;  g_d1[(n0 + 1) * 2 + head] = d1;
        g_s1[(n0 + 2) * 2 + head] = s2;  g_d1[(n0 + 2) * 2 + head] = d2;
        g_s1[(n0 + 3) * 2 + head] = s3;  g_d1[(n0 + 3) * 2 + head] = d3;
    }
}

// ---- scan: padded exclusive scan -> off/cur/dend; re-zeroes deg ---------------
__global__ void k_scan() {
    __shared__ int ps[1024];
    const int CH = (N_NODES + 1023) / 1024;   // 49
    int t = threadIdx.x;
    int b = t * CH;
    int e = min(b + CH, N_NODES);
    int s = 0;
#pragma unroll 4
    for (int i = b; i < e; i++) s += (g_deg[i] + 3) & ~3;
    ps[t] = s;
    __syncthreads();
    for (int off = 1; off < 1024; off <<= 1) {
        int v = (t >= off) ? ps[t - off] : 0;
        __syncthreads();
        ps[t] += v;
        __syncthreads();
    }
    int run = (t == 0) ? 0 : ps[t - 1];
    for (int i = b; i < e; i++) {
        int d = g_deg[i];
        g_off[i]  = run;
        g_cur[i]  = run;
        g_dend[i] = run + d;
        g_deg[i]  = 0;
        run += (d + 3) & ~3;
    }
}

// ---- scatter AoS: one 16B slot per edge {src, w1a, w1b, dst}  |  pad fill -----
__global__ void k_scatterA(const int* __restrict__ ei32) {
    if (blockIdx.x >= HIST_BLKS) {
        int node = (blockIdx.x - HIST_BLKS) * 256 + threadIdx.x;
        if (node >= N_NODES) return;
        int dend = g_dend[node];
        int pend = g_off[node] + ((dend - g_off[node] + 3) & ~3);
        for (int p = dend; p < pend; p++)
            g_slot[p] = make_int4(0, 0, 0, -1);   // w=0.0f bits, src=0 (safe), pad mark
        return;
    }
    int base = (blockIdx.x * 256 + threadIdx.x) * 4;
    int is64 = detect64(ei32);
#pragma unroll
    for (int k = 0; k < 4; k++) {
        int i = base + k;
        if (i >= ET) return;
        int src, dst;
        if (i < N_EDGES) {
            if (is64) { src = ei32[2 * i]; dst = ei32[2 * (N_EDGES + i)]; }
            else      { src = ei32[i];     dst = ei32[N_EDGES + i]; }
        } else {
            src = dst = i - N_EDGES;
        }
        int pos = atomicAdd(&g_cur[dst], 1);
        float2 sv = ((const float2*)g_s1)[src];
        float2 dv = ((const float2*)g_d1)[dst];
        float l0 = sv.x + dv.x;
        float l1 = sv.y + dv.y;
        l0 = (l0 >= 0.f) ? l0 : SLOPE * l0;
        l1 = (l1 >= 0.f) ? l1 : SLOPE * l1;
        g_slot[pos] = make_int4(src, __float_as_int(__expf(l0)),
                                     __float_as_int(__expf(l1)), dst);
    }
}

// ---- gather layer 1: weighted gather from AoS slots + elu (warp / node) ------
__global__ void k_gather1(const float* __restrict__ bias1) {
    int node = blockIdx.x * (blockDim.x >> 5) + (threadIdx.x >> 5);
    int lane = threadIdx.x & 31;
    if (node >= N_NODES) return;
    int beg = g_off[node];
    int n4  = (g_dend[node] - beg + 3) >> 2;
    int head = lane >> 4;
    float acc = 0.f, z = 0.f;
#pragma unroll 2
    for (int it = 0; it < n4; it++) {
        int4 e0 = g_slot[beg + it * 4 + 0];
        int4 e1 = g_slot[beg + it * 4 + 1];
        int4 e2 = g_slot[beg + it * 4 + 2];
        int4 e3 = g_slot[beg + it * 4 + 3];
        float w0 = __int_as_float(head ? e0.z : e0.y);
        float w1 = __int_as_float(head ? e1.z : e1.y);
        float w2 = __int_as_float(head ? e2.z : e2.y);
        float w3 = __int_as_float(head ? e3.z : e3.y);
        float h0 = __half2float(g_h1h[e0.x * D1 + lane]);
        float h1 = __half2float(g_h1h[e1.x * D1 + lane]);
        float h2 = __half2float(g_h1h[e2.x * D1 + lane]);
        float h3 = __half2float(g_h1h[e3.x * D1 + lane]);
        acc += h0 * w0 + h1 * w1 + h2 * w2 + h3 * w3;
        z   += (w0 + w1) + (w2 + w3);
    }
    float v = acc / (z + 1e-16f) + bias1[lane];
    g_h1e[node * D1 + lane] = (v > 0.f) ? v : expm1f(v);
}

// ---- gemm2 + sd2 fused (16 threads / node pair) ------------------------------
__global__ void k_gemm2(const float* __restrict__ W2,
                        const float* __restrict__ a_src, const float* __restrict__ a_dst) {
    __shared__ float4 Ws4[D1 * (D2 / 4)];   // 8 KB
    for (int i = threadIdx.x; i < D1 * (D2 / 4); i += blockDim.x)
        Ws4[i] = ((const float4*)W2)[i];
    __syncthreads();

    int tid  = blockIdx.x * blockDim.x + threadIdx.x;
    int pair = tid >> 4;
    int sub  = tid & 15;
    if (pair >= N_NODES / 2) return;
    int n0 = pair * 2, n1 = n0 + 1;

    const float4* hr0 = (const float4*)(g_h1e + n0 * D1);
    const float4* hr1 = (const float4*)(g_h1e + n1 * D1);
    float4 acc0 = make_float4(0.f, 0.f, 0.f, 0.f);
    float4 acc1 = make_float4(0.f, 0.f, 0.f, 0.f);
#pragma unroll
    for (int k4 = 0; k4 < 8; k4++) {
        float4 xa = hr0[k4];
        float4 xb = hr1[k4];
        float4 w0 = Ws4[(k4 * 4 + 0) * 16 + sub];
        float4 w1 = Ws4[(k4 * 4 + 1) * 16 + sub];
        float4 w2 = Ws4[(k4 * 4 + 2) * 16 + sub];
        float4 w3 = Ws4[(k4 * 4 + 3) * 16 + sub];
        acc0.x += xa.x * w0.x + xa.y * w1.x + xa.z * w2.x + xa.w * w3.x;
        acc0.y += xa.x * w0.y + xa.y * w1.y + xa.z * w2.y + xa.w * w3.y;
        acc0.z += xa.x * w0.z + xa.y * w1.z + xa.z * w2.z + xa.w * w3.z;
        acc0.w += xa.x * w0.w + xa.y * w1.w + xa.z * w2.w + xa.w * w3.w;
        acc1.x += xb.x * w0.x + xb.y * w1.x + xb.z * w2.x + xb.w * w3.x;
        acc1.y += xb.x * w0.y + xb.y * w1.y + xb.z * w2.y + xb.w * w3.y;
        acc1.z += xb.x * w0.z + xb.y * w1.z + xb.z * w2.z + xb.w * w3.z;
        acc1.w += xb.x * w0.w + xb.y * w1.w + xb.z * w2.w + xb.w * w3.w;
    }
    g_h2h[n0 * 32 + sub * 2]     = __floats2half2_rn(acc0.x, acc0.y);
    g_h2h[n0 * 32 + sub * 2 + 1] = __floats2half2_rn(acc0.z, acc0.w);
    g_h2h[n1 * 32 + sub * 2]     = __floats2half2_rn(acc1.x, acc1.y);
    g_h2h[n1 * 32 + sub * 2 + 1] = __floats2half2_rn(acc1.z, acc1.w);

    float4 as = ((const float4*)a_src)[sub];
    float4 ad = ((const float4*)a_dst)[sub];
    float s0 = acc0.x * as.x + acc0.y * as.y + acc0.z * as.z + acc0.w * as.w;
    float d0 = acc0.x * ad.x + acc0.y * ad.y + acc0.z * ad.z + acc0.w * ad.w;
    float s1 = acc1.x * as.x + acc1.y * as.y + acc1.z * as.z + acc1.w * as.w;
    float d1 = acc1.x * ad.x + acc1.y * ad.y + acc1.z * ad.z + acc1.w * ad.w;
#pragma unroll
    for (int o = 8; o; o >>= 1) {
        s0 += __shfl_down_sync(0xffffffffu, s0, o, 16);
        d0 += __shfl_down_sync(0xffffffffu, d0, o, 16);
        s1 += __shfl_down_sync(0xffffffffu, s1, o, 16);
        d1 += __shfl_down_sync(0xffffffffu, d1, o, 16);
    }
    if (sub == 0) {
        g_s2[n0] = s0;
        g_d2[n0] = d0;
        g_s2[n1] = s1;
        g_d2[n1] = d1;
    }
}

// ---- layer2 edge weights (slot-parallel, coalesced AoS reads) ----------------
__global__ void k_w2() {
    int p = blockIdx.x * blockDim.x + threadIdx.x;
    if (p >= ESRC_SZ) return;
    int4 sl = g_slot[p];
    float w = 0.f;
    if (sl.w >= 0) {
        float l = g_s2[sl.x] + g_d2[sl.w];
        l = (l >= 0.f) ? l : SLOPE * l;
        w = __expf(l);
    }
    g_w2[p] = w;
}

// ---- gather layer 2: weighted gather (warp / node, half2 lanes) --------------
__global__ void k_gather2(const float* __restrict__ bias2, float* __restrict__ out) {
    int node = blockIdx.x * (blockDim.x >> 5) + (threadIdx.x >> 5);
    int lane = threadIdx.x & 31;
    if (node >= N_NODES) return;
    int beg = g_off[node];
    int n4  = (g_dend[node] - beg + 3) >> 2;
    const float4* wp = (const float4*)(g_w2 + beg);
    float ax = 0.f, ay = 0.f, z = 0.f;
#pragma unroll 2
    for (int it = 0; it < n4; it++) {
        int s0 = g_slot[beg + it * 4 + 0].x;
        int s1 = g_slot[beg + it * 4 + 1].x;
        int s2 = g_slot[beg + it * 4 + 2].x;
        int s3 = g_slot[beg + it * 4 + 3].x;
        float4 wv = wp[it];
        float2 h0 = __half22float2(g_h2h[s0 * 32 + lane]);
        float2 h1 = __half22float2(g_h2h[s1 * 32 + lane]);
        float2 h2 = __half22float2(g_h2h[s2 * 32 + lane]);
        float2 h3 = __half22float2(g_h2h[s3 * 32 + lane]);
        ax += h0.x * wv.x + h1.x * wv.y + h2.x * wv.z + h3.x * wv.w;
        ay += h0.y * wv.x + h1.y * wv.y + h2.y * wv.z + h3.y * wv.w;
        z  += (wv.x + wv.y) + (wv.z + wv.w);
    }
    float inv = 1.f / (z + 1e-16f);
    float2 o2;
    o2.x = ax * inv + bias2[lane * 2];
    o2.y = ay * inv + bias2[lane * 2 + 1];
    *(float2*)(out + node * D2 + lane * 2) = o2;
}

extern "C" void kernel_launch(void* const* d_in, const int* in_sizes, int n_in,
                              void* d_out, int out_size) {
    const float* x     = (const float*)d_in[0];
    const int*   ei32  = (const int*)d_in[1];
    const float* W1    = (const float*)d_in[2];
    const float* asrc1 = (const float*)d_in[3];
    const float* adst1 = (const float*)d_in[4];
    const float* bias1 = (const float*)d_in[5];
    const float* W2    = (const float*)d_in[6];
    const float* asrc2 = (const float*)d_in[7];
    const float* adst2 = (const float*)d_in[8];
    const float* bias2 = (const float*)d_in[9];
    float* out = (float*)d_out;

    const int T = 256;

    k_gemm1hist<<<GEMM1_BLKS + HIST_BLKS, T>>>(x, W1, asrc1, adst1, ei32);  // 1
    k_scan<<<1, 1024>>>();                                                   // 2
    k_scatterA<<<HIST_BLKS + PAD_BLKS, T>>>(ei32);                           // 3
    k_gather1<<<(N_NODES + 7) / 8, T>>>(bias1);                              // 4 <- profiled
    k_gemm2<<<((N_NODES / 2) * 16 + T - 1) / T, T>>>(W2, asrc2, adst2);      // 5
    k_w2<<<(ESRC_SZ + T - 1) / T, T>>>();                                    // 6
    k_gather2<<<(N_NODES + 7) / 8, T>>>(bias2, out);                         // 7
}

// round 13
// speedup vs baseline: 1.3702x; 1.2661x over previous
#include <cuda_runtime.h>
#include <cuda_fp16.h>

#define N_NODES 50000
#define N_EDGES 800000
#define ET (N_EDGES + N_NODES)        // edges + self loops
#define ESRC_SZ (ET + 3 * N_NODES)    // padded CSR capacity
#define IN_DIM 128
#define D1 32
#define D2 64
#define SLOPE 0.2f
#define SENT N_NODES                  // sentinel node id

// ---------------- scratch ----------------
__device__ __align__(16) __half  g_h1h[(N_NODES + 1) * D1];  // x@W1, fp16 (+sentinel=0)
__device__ float g_s1[(N_NODES + 1) * 2];                    // sentinel = -1e30
__device__ float g_d1[N_NODES * 2];
__device__ __align__(16) float g_h1e[N_NODES * D1];          // elu(gat1 out), fp32
__device__ __align__(16) __half2 g_h2h[(N_NODES + 1) * 32];  // layer2 feats fp16 (+sent=0)
__device__ float g_s2[N_NODES + 1];                          // sentinel = -1e30
__device__ float g_d2[N_NODES];
__device__ int   g_deg[N_NODES];
__device__ int   g_off[N_NODES + 1];
__device__ int   g_cur[N_NODES];
__device__ __align__(16) int g_esrc[ESRC_SZ];                // CSR (padded, sentinel-filled)
__device__ int   g_is64;

// ---------------- init: zero deg, sentinel fill, detect dtype ----------------
__global__ void k_init(const int* __restrict__ ei32) {
    int i = blockIdx.x * blockDim.x + threadIdx.x;
    int stride = gridDim.x * blockDim.x;
    for (int j = i; j < N_NODES; j += stride) g_deg[j] = 0;
    for (int j = i; j < ESRC_SZ; j += stride) g_esrc[j] = SENT;
    if (i < D1) g_h1h[SENT * D1 + i] = __float2half(0.f);
    if (i < 32) g_h2h[SENT * 32 + i] = __floats2half2_rn(0.f, 0.f);
    if (i == 0) {
        int odd_nonzero = 0;
#pragma unroll
        for (int j = 1; j < 128; j += 2) odd_nonzero |= (ei32[j] != 0);
        g_is64 = odd_nonzero ? 0 : 1;
        g_s1[2 * SENT] = -1e30f;
        g_s1[2 * SENT + 1] = -1e30f;
        g_s2[SENT] = -1e30f;
    }
}

// ---------------- histogram of dst degrees (4 edges / thread) -----------------
__global__ void k_hist(const int* __restrict__ ei32) {
    int base = (blockIdx.x * blockDim.x + threadIdx.x) * 4;
    int is64 = g_is64;
#pragma unroll
    for (int k = 0; k < 4; k++) {
        int i = base + k;
        if (i >= ET) return;
        int dst;
        if (i < N_EDGES) dst = is64 ? ei32[2 * (N_EDGES + i)] : ei32[N_EDGES + i];
        else             dst = i - N_EDGES;
        atomicAdd(&g_deg[dst], 1);
    }
}

// exclusive scan of padded degrees -> g_off / g_cur, single block of 1024
__global__ void k_scan() {
    __shared__ int ps[1024];
    const int CH = (N_NODES + 1023) / 1024;   // 49
    int t = threadIdx.x;
    int b = t * CH;
    int e = min(b + CH, N_NODES);
    int s = 0;
#pragma unroll 4
    for (int i = b; i < e; i++) s += (g_deg[i] + 3) & ~3;
    ps[t] = s;
    __syncthreads();
    for (int off = 1; off < 1024; off <<= 1) {
        int v = (t >= off) ? ps[t - off] : 0;
        __syncthreads();
        ps[t] += v;
        __syncthreads();
    }
    int run = (t == 0) ? 0 : ps[t - 1];
    for (int i = b; i < e; i++) {
        g_off[i] = run;
        g_cur[i] = run;
        run += (g_deg[i] + 3) & ~3;
    }
    if (t == 1023) g_off[N_NODES] = ps[1023];
}

// ---------------- scatter src indices into CSR buckets (4 / thread) -----------
__global__ void k_scatter(const int* __restrict__ ei32) {
    int base = (blockIdx.x * blockDim.x + threadIdx.x) * 4;
    int is64 = g_is64;
#pragma unroll
    for (int k = 0; k < 4; k++) {
        int i = base + k;
        if (i >= ET) return;
        int src, dst;
        if (i < N_EDGES) {
            if (is64) { src = ei32[2 * i]; dst = ei32[2 * (N_EDGES + i)]; }
            else      { src = ei32[i];     dst = ei32[N_EDGES + i]; }
        } else {
            src = dst = i - N_EDGES;
        }
        int pos = atomicAdd(&g_cur[dst], 1);
        g_esrc[pos] = src;
    }
}

// ---------------- gemm1 + sd1 fused (8 threads / node QUAD, 4 cols x 4 nodes) --
__global__ void __launch_bounds__(256) k_gemm1(
        const float* __restrict__ x, const float* __restrict__ W1,
        const float* __restrict__ a_src, const float* __restrict__ a_dst) {
    __shared__ float4 Ws4[IN_DIM * (D1 / 4)];   // 16 KB
    for (int i = threadIdx.x; i < IN_DIM * (D1 / 4); i += blockDim.x)
        Ws4[i] = ((const float4*)W1)[i];
    __syncthreads();

    int tid  = blockIdx.x * blockDim.x + threadIdx.x;
    int quad = tid >> 3;
    int sub  = tid & 7;
    if (quad >= N_NODES / 4) return;   // 50000 % 4 == 0
    int n0 = quad * 4;

    const float4* x0p = (const float4*)(x + (n0 + 0) * IN_DIM);
    const float4* x1p = (const float4*)(x + (n0 + 1) * IN_DIM);
    const float4* x2p = (const float4*)(x + (n0 + 2) * IN_DIM);
    const float4* x3p = (const float4*)(x + (n0 + 3) * IN_DIM);
    float4 a0 = make_float4(0.f, 0.f, 0.f, 0.f);
    float4 a1 = a0, a2 = a0, a3 = a0;
#pragma unroll 2
    for (int k4 = 0; k4 < 32; k4++) {
        float4 w0 = Ws4[(k4 * 4 + 0) * 8 + sub];
        float4 w1 = Ws4[(k4 * 4 + 1) * 8 + sub];
        float4 w2 = Ws4[(k4 * 4 + 2) * 8 + sub];
        float4 w3 = Ws4[(k4 * 4 + 3) * 8 + sub];
        float4 xv;
        xv = x0p[k4];
        a0.x += xv.x * w0.x + xv.y * w1.x + xv.z * w2.x + xv.w * w3.x;
        a0.y += xv.x * w0.y + xv.y * w1.y + xv.z * w2.y + xv.w * w3.y;
        a0.z += xv.x * w0.z + xv.y * w1.z + xv.z * w2.z + xv.w * w3.z;
        a0.w += xv.x * w0.w + xv.y * w1.w + xv.z * w2.w + xv.w * w3.w;
        xv = x1p[k4];
        a1.x += xv.x * w0.x + xv.y * w1.x + xv.z * w2.x + xv.w * w3.x;
        a1.y += xv.x * w0.y + xv.y * w1.y + xv.z * w2.y + xv.w * w3.y;
        a1.z += xv.x * w0.z + xv.y * w1.z + xv.z * w2.z + xv.w * w3.z;
        a1.w += xv.x * w0.w + xv.y * w1.w + xv.z * w2.w + xv.w * w3.w;
        xv = x2p[k4];
        a2.x += xv.x * w0.x + xv.y * w1.x + xv.z * w2.x + xv.w * w3.x;
        a2.y += xv.x * w0.y + xv.y * w1.y + xv.z * w2.y + xv.w * w3.y;
        a2.z += xv.x * w0.z + xv.y * w1.z + xv.z * w2.z + xv.w * w3.z;
        a2.w += xv.x * w0.w + xv.y * w1.w + xv.z * w2.w + xv.w * w3.w;
        xv = x3p[k4];
        a3.x += xv.x * w0.x + xv.y * w1.x + xv.z * w2.x + xv.w * w3.x;
        a3.y += xv.x * w0.y + xv.y * w1.y + xv.z * w2.y + xv.w * w3.y;
        a3.z += xv.x * w0.z + xv.y * w1.z + xv.z * w2.z + xv.w * w3.z;
        a3.w += xv.x * w0.w + xv.y * w1.w + xv.z * w2.w + xv.w * w3.w;
    }
    // store fp16 features (scores stay fp32, computed from fp32 accs)
    __half2* h1p = (__half2*)g_h1h;
    h1p[(n0 + 0) * 16 + sub * 2]     = __floats2half2_rn(a0.x, a0.y);
    h1p[(n0 + 0) * 16 + sub * 2 + 1] = __floats2half2_rn(a0.z, a0.w);
    h1p[(n0 + 1) * 16 + sub * 2]     = __floats2half2_rn(a1.x, a1.y);
    h1p[(n0 + 1) * 16 + sub * 2 + 1] = __floats2half2_rn(a1.z, a1.w);
    h1p[(n0 + 2) * 16 + sub * 2]     = __floats2half2_rn(a2.x, a2.y);
    h1p[(n0 + 2) * 16 + sub * 2 + 1] = __floats2half2_rn(a2.z, a2.w);
    h1p[(n0 + 3) * 16 + sub * 2]     = __floats2half2_rn(a3.x, a3.y);
    h1p[(n0 + 3) * 16 + sub * 2 + 1] = __floats2half2_rn(a3.z, a3.w);

    float4 as = ((const float4*)a_src)[sub];
    float4 ad = ((const float4*)a_dst)[sub];
    float s0 = a0.x * as.x + a0.y * as.y + a0.z * as.z + a0.w * as.w;
    float d0 = a0.x * ad.x + a0.y * ad.y + a0.z * ad.z + a0.w * ad.w;
    float s1 = a1.x * as.x + a1.y * as.y + a1.z * as.z + a1.w * as.w;
    float d1 = a1.x * ad.x + a1.y * ad.y + a1.z * ad.z + a1.w * ad.w;
    float s2 = a2.x * as.x + a2.y * as.y + a2.z * as.z + a2.w * as.w;
    float d2 = a2.x * ad.x + a2.y * ad.y + a2.z * ad.z + a2.w * ad.w;
    float s3 = a3.x * as.x + a3.y * as.y + a3.z * as.z + a3.w * as.w;
    float d3 = a3.x * ad.x + a3.y * ad.y + a3.z * ad.z + a3.w * ad.w;
#pragma unroll
    for (int o = 2; o; o >>= 1) {
        s0 += __shfl_down_sync(0xffffffffu, s0, o, 4);
        d0 += __shfl_down_sync(0xffffffffu, d0, o, 4);
        s1 += __shfl_down_sync(0xffffffffu, s1, o, 4);
        d1 += __shfl_down_sync(0xffffffffu, d1, o, 4);
        s2 += __shfl_down_sync(0xffffffffu, s2, o, 4);
        d2 += __shfl_down_sync(0xffffffffu, d2, o, 4);
        s3 += __shfl_down_sync(0xffffffffu, s3, o, 4);
        d3 += __shfl_down_sync(0xffffffffu, d3, o, 4);
    }
    if ((sub & 3) == 0) {
        int head = sub >> 2;
        g_s1[(n0 + 0) * 2 + head] = s0;  g_d1[(n0 + 0) * 2 + head] = d0;
        g_s1[(n0 + 1) * 2 + head] = s1;  g_d1[(n0 + 1) * 2 + head] = d1;
        g_s1[(n0 + 2) * 2 + head] = s2;  g_d1[(n0 + 2) * 2 + head] = d2;
        g_s1[(n0 + 3) * 2 + head] = s3;  g_d1[(n0 + 3) * 2 + head] = d3;
    }
}

// ---------------- gather layer 1 + finalize + elu (warp / node, fp16 rows) ----
__global__ void k_gather1(const float* __restrict__ bias1) {
    int node = blockIdx.x * (blockDim.x >> 5) + (threadIdx.x >> 5);
    int lane = threadIdx.x & 31;
    if (node >= N_NODES) return;
    int beg = g_off[node];
    int n4  = (g_off[node + 1] - beg) >> 2;   // >= 1
    int head = lane >> 4;
    float dd = g_d1[node * 2 + head];
    float acc = 0.f, z = 0.f;

    const int4* ep = (const int4*)(g_esrc + beg);
    int4 sv = ep[0];
    for (int it = 0; it < n4; it++) {
        int4 nx = (it + 1 < n4) ? ep[it + 1] : sv;
        float l0 = g_s1[sv.x * 2 + head] + dd;
        float l1 = g_s1[sv.y * 2 + head] + dd;
        float l2 = g_s1[sv.z * 2 + head] + dd;
        float l3 = g_s1[sv.w * 2 + head] + dd;
        float h0 = __half2float(g_h1h[sv.x * D1 + lane]);
        float h1 = __half2float(g_h1h[sv.y * D1 + lane]);
        float h2 = __half2float(g_h1h[sv.z * D1 + lane]);
        float h3 = __half2float(g_h1h[sv.w * D1 + lane]);
        l0 = (l0 >= 0.f) ? l0 : SLOPE * l0;
        l1 = (l1 >= 0.f) ? l1 : SLOPE * l1;
        l2 = (l2 >= 0.f) ? l2 : SLOPE * l2;
        l3 = (l3 >= 0.f) ? l3 : SLOPE * l3;
        float x0 = __expf(l0), x1 = __expf(l1), x2 = __expf(l2), x3 = __expf(l3);
        acc += h0 * x0 + h1 * x1 + h2 * x2 + h3 * x3;
        z   += (x0 + x1) + (x2 + x3);
        sv = nx;
    }
    float v = acc / (z + 1e-16f) + bias1[lane];
    g_h1e[node * D1 + lane] = (v > 0.f) ? v : expm1f(v);
}

// ---------------- gemm2 + sd2 fused (16 threads / node pair) ------------------
__global__ void k_gemm2(const float* __restrict__ W2,
                        const float* __restrict__ a_src, const float* __restrict__ a_dst) {
    __shared__ float4 Ws4[D1 * (D2 / 4)];   // 8 KB
    for (int i = threadIdx.x; i < D1 * (D2 / 4); i += blockDim.x)
        Ws4[i] = ((const float4*)W2)[i];
    __syncthreads();

    int tid  = blockIdx.x * blockDim.x + threadIdx.x;
    int pair = tid >> 4;
    int sub  = tid & 15;
    if (pair >= N_NODES / 2) return;
    int n0 = pair * 2, n1 = n0 + 1;

    const float4* hr0 = (const float4*)(g_h1e + n0 * D1);
    const float4* hr1 = (const float4*)(g_h1e + n1 * D1);
    float4 acc0 = make_float4(0.f, 0.f, 0.f, 0.f);
    float4 acc1 = make_float4(0.f, 0.f, 0.f, 0.f);
#pragma unroll
    for (int k4 = 0; k4 < 8; k4++) {
        float4 xa = hr0[k4];
        float4 xb = hr1[k4];
        float4 w0 = Ws4[(k4 * 4 + 0) * 16 + sub];
        float4 w1 = Ws4[(k4 * 4 + 1) * 16 + sub];
        float4 w2 = Ws4[(k4 * 4 + 2) * 16 + sub];
        float4 w3 = Ws4[(k4 * 4 + 3) * 16 + sub];
        acc0.x += xa.x * w0.x + xa.y * w1.x + xa.z * w2.x + xa.w * w3.x;
        acc0.y += xa.x * w0.y + xa.y * w1.y + xa.z * w2.y + xa.w * w3.y;
        acc0.z += xa.x * w0.z + xa.y * w1.z + xa.z * w2.z + xa.w * w3.z;
        acc0.w += xa.x * w0.w + xa.y * w1.w + xa.z * w2.w + xa.w * w3.w;
        acc1.x += xb.x * w0.x + xb.y * w1.x + xb.z * w2.x + xb.w * w3.x;
        acc1.y += xb.x * w0.y + xb.y * w1.y + xb.z * w2.y + xb.w * w3.y;
        acc1.z += xb.x * w0.z + xb.y * w1.z + xb.z * w2.z + xb.w * w3.z;
        acc1.w += xb.x * w0.w + xb.y * w1.w + xb.z * w2.w + xb.w * w3.w;
    }
    g_h2h[n0 * 32 + sub * 2]     = __floats2half2_rn(acc0.x, acc0.y);
    g_h2h[n0 * 32 + sub * 2 + 1] = __floats2half2_rn(acc0.z, acc0.w);
    g_h2h[n1 * 32 + sub * 2]     = __floats2half2_rn(acc1.x, acc1.y);
    g_h2h[n1 * 32 + sub * 2 + 1] = __floats2half2_rn(acc1.z, acc1.w);

    float4 as = ((const float4*)a_src)[sub];
    float4 ad = ((const float4*)a_dst)[sub];
    float s0 = acc0.x * as.x + acc0.y * as.y + acc0.z * as.z + acc0.w * as.w;
    float d0 = acc0.x * ad.x + acc0.y * ad.y + acc0.z * ad.z + acc0.w * ad.w;
    float s1 = acc1.x * as.x + acc1.y * as.y + acc1.z * as.z + acc1.w * as.w;
    float d1 = acc1.x * ad.x + acc1.y * ad.y + acc1.z * ad.z + acc1.w * ad.w;
#pragma unroll
    for (int o = 8; o; o >>= 1) {
        s0 += __shfl_down_sync(0xffffffffu, s0, o, 16);
        d0 += __shfl_down_sync(0xffffffffu, d0, o, 16);
        s1 += __shfl_down_sync(0xffffffffu, s1, o, 16);
        d1 += __shfl_down_sync(0xffffffffu, d1, o, 16);
    }
    if (sub == 0) {
        g_s2[n0] = s0;
        g_d2[n0] = d0;
        g_s2[n1] = s1;
        g_d2[n1] = d1;
    }
}

// ---------------- gather layer 2 (warp / node, half2 lanes) -------------------
__global__ void k_gather2(const float* __restrict__ bias2, float* __restrict__ out) {
    int node = blockIdx.x * (blockDim.x >> 5) + (threadIdx.x >> 5);
    int lane = threadIdx.x & 31;
    if (node >= N_NODES) return;
    int beg = g_off[node];
    int n4  = (g_off[node + 1] - beg) >> 2;
    float dd = g_d2[node];
    float ax = 0.f, ay = 0.f, z = 0.f;

    const int4* ep = (const int4*)(g_esrc + beg);
    int4 sv = ep[0];
    for (int it = 0; it < n4; it++) {
        int4 nx = (it + 1 < n4) ? ep[it + 1] : sv;
        float l0 = g_s2[sv.x] + dd;
        float l1 = g_s2[sv.y] + dd;
        float l2 = g_s2[sv.z] + dd;
        float l3 = g_s2[sv.w] + dd;
        float2 h0 = __half22float2(g_h2h[sv.x * 32 + lane]);
        float2 h1 = __half22float2(g_h2h[sv.y * 32 + lane]);
        float2 h2 = __half22float2(g_h2h[sv.z * 32 + lane]);
        float2 h3 = __half22float2(g_h2h[sv.w * 32 + lane]);
        l0 = (l0 >= 0.f) ? l0 : SLOPE * l0;
        l1 = (l1 >= 0.f) ? l1 : SLOPE * l1;
        l2 = (l2 >= 0.f) ? l2 : SLOPE * l2;
        l3 = (l3 >= 0.f) ? l3 : SLOPE * l3;
        float x0 = __expf(l0), x1 = __expf(l1), x2 = __expf(l2), x3 = __expf(l3);
        ax += h0.x * x0 + h1.x * x1 + h2.x * x2 + h3.x * x3;
        ay += h0.y * x0 + h1.y * x1 + h2.y * x2 + h3.y * x3;
        z  += (x0 + x1) + (x2 + x3);
        sv = nx;
    }
    float inv = 1.f / (z + 1e-16f);
    float2 o2;
    o2.x = ax * inv + bias2[lane * 2];
    o2.y = ay * inv + bias2[lane * 2 + 1];
    *(float2*)(out + node * D2 + lane * 2) = o2;
}

extern "C" void kernel_launch(void* const* d_in, const int* in_sizes, int n_in,
                              void* d_out, int out_size) {
    const float* x     = (const float*)d_in[0];
    const int*   ei32  = (const int*)d_in[1];
    const float* W1    = (const float*)d_in[2];
    const float* asrc1 = (const float*)d_in[3];
    const float* adst1 = (const float*)d_in[4];
    const float* bias1 = (const float*)d_in[5];
    const float* W2    = (const float*)d_in[6];
    const float* asrc2 = (const float*)d_in[7];
    const float* adst2 = (const float*)d_in[8];
    const float* bias2 = (const float*)d_in[9];
    float* out = (float*)d_out;

    const int T = 256;

    static cudaStream_t s2 = nullptr;
    static cudaEvent_t  evF = nullptr, evJ = nullptr;
    if (!s2) {
        cudaStreamCreateWithFlags(&s2, cudaStreamNonBlocking);
        cudaEventCreateWithFlags(&evF, cudaEventDisableTiming);
        cudaEventCreateWithFlags(&evJ, cudaEventDisableTiming);
    }

    cudaEventRecord(evF, 0);
    cudaStreamWaitEvent(s2, evF, 0);

    k_init<<<1024, T>>>(ei32);                                              // 1
    k_hist<<<((ET + 3) / 4 + T - 1) / T, T>>>(ei32);                        // 2
    k_gemm1<<<((N_NODES / 4) * 8 + T - 1) / T, T, 0, s2>>>(x, W1, asrc1, adst1); // 3 (s2)
    cudaEventRecord(evJ, s2);
    k_scan<<<1, 1024>>>();                                                   // 4 <- profiled
    k_scatter<<<((ET + 3) / 4 + T - 1) / T, T>>>(ei32);                      // 5

    cudaStreamWaitEvent(0, evJ, 0);
    k_gather1<<<(N_NODES + 7) / 8, T>>>(bias1);                              // 6
    k_gemm2<<<((N_NODES / 2) * 16 + T - 1) / T, T>>>(W2, asrc2, adst2);      // 7
    k_gather2<<<(N_NODES + 7) / 8, T>>>(bias2, out);                         // 8
}

// round 14
// speedup vs baseline: 2.1877x; 1.5967x over previous
#include <cuda_runtime.h>
#include <cuda_fp16.h>

#define N_NODES 50000
#define N_EDGES 800000
#define ET (N_EDGES + N_NODES)        // edges + self loops
#define ESRC_SZ (ET + 3 * N_NODES)    // padded CSR capacity
#define IN_DIM 128
#define D1 32
#define D2 64
#define SLOPE 0.2f
#define SENT N_NODES                  // sentinel node id
#define SCAN_BLKS ((N_NODES + 255) / 256)   // 196

// ---------------- scratch ----------------
__device__ __align__(16) __half  g_h1h[(N_NODES + 1) * D1];  // x@W1, fp16 (+sentinel=0)
__device__ float g_s1[(N_NODES + 1) * 2];                    // sentinel = -1e30
__device__ float g_d1[N_NODES * 2];
__device__ __align__(16) float g_h1e[N_NODES * D1];          // elu(gat1 out), fp32
__device__ __align__(16) __half2 g_h2h[(N_NODES + 1) * 32];  // layer2 feats fp16 (+sent=0)
__device__ float g_s2[N_NODES + 1];                          // sentinel = -1e30
__device__ float g_d2[N_NODES];
__device__ int   g_deg[N_NODES];
__device__ int   g_off[N_NODES + 1];
__device__ int   g_cur[N_NODES];
__device__ int   g_tmpoff[N_NODES];       // within-block exclusive prefix
__device__ int   g_bsum[SCAN_BLKS];       // per-block totals
__device__ int   g_bpre[256];             // exclusive prefix of block totals
__device__ __align__(16) int g_esrc[ESRC_SZ];                // CSR (padded, sentinel-filled)
__device__ int   g_is64;

// ---------------- init: zero deg, sentinel fill, detect dtype ----------------
__global__ void k_init(const int* __restrict__ ei32) {
    int i = blockIdx.x * blockDim.x + threadIdx.x;
    int stride = gridDim.x * blockDim.x;
    for (int j = i; j < N_NODES; j += stride) g_deg[j] = 0;
    for (int j = i; j < ESRC_SZ; j += stride) g_esrc[j] = SENT;
    if (i < D1) g_h1h[SENT * D1 + i] = __float2half(0.f);
    if (i < 32) g_h2h[SENT * 32 + i] = __floats2half2_rn(0.f, 0.f);
    if (i == 0) {
        int odd_nonzero = 0;
#pragma unroll
        for (int j = 1; j < 128; j += 2) odd_nonzero |= (ei32[j] != 0);
        g_is64 = odd_nonzero ? 0 : 1;
        g_s1[2 * SENT] = -1e30f;
        g_s1[2 * SENT + 1] = -1e30f;
        g_s2[SENT] = -1e30f;
    }
}

// ---------------- histogram of dst degrees (4 edges / thread) -----------------
__global__ void k_hist(const int* __restrict__ ei32) {
    int base = (blockIdx.x * blockDim.x + threadIdx.x) * 4;
    int is64 = g_is64;
#pragma unroll
    for (int k = 0; k < 4; k++) {
        int i = base + k;
        if (i >= ET) return;
        int dst;
        if (i < N_EDGES) dst = is64 ? ei32[2 * (N_EDGES + i)] : ei32[N_EDGES + i];
        else             dst = i - N_EDGES;
        atomicAdd(&g_deg[dst], 1);
    }
}

// ---------------- 3-phase decoupled scan of padded degrees --------------------
__global__ void k_scanA() {
    __shared__ int sh[256];
    int i = blockIdx.x * 256 + threadIdx.x;
    int v = (i < N_NODES) ? ((g_deg[i] + 3) & ~3) : 0;
    int incl = v;
#pragma unroll
    for (int off = 1; off < 256; off <<= 1) {
        sh[threadIdx.x] = incl;
        __syncthreads();
        int add = (threadIdx.x >= off) ? sh[threadIdx.x - off] : 0;
        __syncthreads();
        incl += add;
    }
    if (i < N_NODES) g_tmpoff[i] = incl - v;
    if (threadIdx.x == 255) g_bsum[blockIdx.x] = incl;
}

__global__ void k_scanB() {
    __shared__ int sh[256];
    int t = threadIdx.x;
    int v = (t < SCAN_BLKS) ? g_bsum[t] : 0;
    int incl = v;
#pragma unroll
    for (int off = 1; off < 256; off <<= 1) {
        sh[t] = incl;
        __syncthreads();
        int add = (t >= off) ? sh[t - off] : 0;
        __syncthreads();
        incl += add;
    }
    g_bpre[t] = incl - v;
}

__global__ void k_scanC() {
    int i = blockIdx.x * 256 + threadIdx.x;
    if (i >= N_NODES) return;
    int off = g_tmpoff[i] + g_bpre[blockIdx.x];
    g_off[i] = off;
    g_cur[i] = off;
    if (i == N_NODES - 1) g_off[N_NODES] = off + ((g_deg[i] + 3) & ~3);
}

// ---------------- scatter src indices into CSR buckets (4 / thread) -----------
__global__ void k_scatter(const int* __restrict__ ei32) {
    int base = (blockIdx.x * blockDim.x + threadIdx.x) * 4;
    int is64 = g_is64;
#pragma unroll
    for (int k = 0; k < 4; k++) {
        int i = base + k;
        if (i >= ET) return;
        int src, dst;
        if (i < N_EDGES) {
            if (is64) { src = ei32[2 * i]; dst = ei32[2 * (N_EDGES + i)]; }
            else      { src = ei32[i];     dst = ei32[N_EDGES + i]; }
        } else {
            src = dst = i - N_EDGES;
        }
        int pos = atomicAdd(&g_cur[dst], 1);
        g_esrc[pos] = src;
    }
}

// ---------------- gemm1 + sd1 fused (8 threads / node QUAD, 4 cols x 4 nodes) --
__global__ void __launch_bounds__(256) k_gemm1(
        const float* __restrict__ x, const float* __restrict__ W1,
        const float* __restrict__ a_src, const float* __restrict__ a_dst) {
    __shared__ float4 Ws4[IN_DIM * (D1 / 4)];   // 16 KB
    for (int i = threadIdx.x; i < IN_DIM * (D1 / 4); i += blockDim.x)
        Ws4[i] = ((const float4*)W1)[i];
    __syncthreads();

    int tid  = blockIdx.x * blockDim.x + threadIdx.x;
    int quad = tid >> 3;
    int sub  = tid & 7;
    if (quad >= N_NODES / 4) return;   // 50000 % 4 == 0
    int n0 = quad * 4;

    const float4* x0p = (const float4*)(x + (n0 + 0) * IN_DIM);
    const float4* x1p = (const float4*)(x + (n0 + 1) * IN_DIM);
    const float4* x2p = (const float4*)(x + (n0 + 2) * IN_DIM);
    const float4* x3p = (const float4*)(x + (n0 + 3) * IN_DIM);
    float4 a0 = make_float4(0.f, 0.f, 0.f, 0.f);
    float4 a1 = a0, a2 = a0, a3 = a0;
#pragma unroll 2
    for (int k4 = 0; k4 < 32; k4++) {
        float4 w0 = Ws4[(k4 * 4 + 0) * 8 + sub];
        float4 w1 = Ws4[(k4 * 4 + 1) * 8 + sub];
        float4 w2 = Ws4[(k4 * 4 + 2) * 8 + sub];
        float4 w3 = Ws4[(k4 * 4 + 3) * 8 + sub];
        float4 xv;
        xv = x0p[k4];
        a0.x += xv.x * w0.x + xv.y * w1.x + xv.z * w2.x + xv.w * w3.x;
        a0.y += xv.x * w0.y + xv.y * w1.y + xv.z * w2.y + xv.w * w3.y;
        a0.z += xv.x * w0.z + xv.y * w1.z + xv.z * w2.z + xv.w * w3.z;
        a0.w += xv.x * w0.w + xv.y * w1.w + xv.z * w2.w + xv.w * w3.w;
        xv = x1p[k4];
        a1.x += xv.x * w0.x + xv.y * w1.x + xv.z * w2.x + xv.w * w3.x;
        a1.y += xv.x * w0.y + xv.y * w1.y + xv.z * w2.y + xv.w * w3.y;
        a1.z += xv.x * w0.z + xv.y * w1.z + xv.z * w2.z + xv.w * w3.z;
        a1.w += xv.x * w0.w + xv.y * w1.w + xv.z * w2.w + xv.w * w3.w;
        xv = x2p[k4];
        a2.x += xv.x * w0.x + xv.y * w1.x + xv.z * w2.x + xv.w * w3.x;
        a2.y += xv.x * w0.y + xv.y * w1.y + xv.z * w2.y + xv.w * w3.y;
        a2.z += xv.x * w0.z + xv.y * w1.z + xv.z * w2.z + xv.w * w3.z;
        a2.w += xv.x * w0.w + xv.y * w1.w + xv.z * w2.w + xv.w * w3.w;
        xv = x3p[k4];
        a3.x += xv.x * w0.x + xv.y * w1.x + xv.z * w2.x + xv.w * w3.x;
        a3.y += xv.x * w0.y + xv.y * w1.y + xv.z * w2.y + xv.w * w3.y;
        a3.z += xv.x * w0.z + xv.y * w1.z + xv.z * w2.z + xv.w * w3.z;
        a3.w += xv.x * w0.w + xv.y * w1.w + xv.z * w2.w + xv.w * w3.w;
    }
    // store fp16 features (scores stay fp32, computed from fp32 accs)
    __half2* h1p = (__half2*)g_h1h;
    h1p[(n0 + 0) * 16 + sub * 2]     = __floats2half2_rn(a0.x, a0.y);
    h1p[(n0 + 0) * 16 + sub * 2 + 1] = __floats2half2_rn(a0.z, a0.w);
    h1p[(n0 + 1) * 16 + sub * 2]     = __floats2half2_rn(a1.x, a1.y);
    h1p[(n0 + 1) * 16 + sub * 2 + 1] = __floats2half2_rn(a1.z, a1.w);
    h1p[(n0 + 2) * 16 + sub * 2]     = __floats2half2_rn(a2.x, a2.y);
    h1p[(n0 + 2) * 16 + sub * 2 + 1] = __floats2half2_rn(a2.z, a2.w);
    h1p[(n0 + 3) * 16 + sub * 2]     = __floats2half2_rn(a3.x, a3.y);
    h1p[(n0 + 3) * 16 + sub * 2 + 1] = __floats2half2_rn(a3.z, a3.w);

    float4 as = ((const float4*)a_src)[sub];
    float4 ad = ((const float4*)a_dst)[sub];
    float s0 = a0.x * as.x + a0.y * as.y + a0.z * as.z + a0.w * as.w;
    float d0 = a0.x * ad.x + a0.y * ad.y + a0.z * ad.z + a0.w * ad.w;
    float s1 = a1.x * as.x + a1.y * as.y + a1.z * as.z + a1.w * as.w;
    float d1 = a1.x * ad.x + a1.y * ad.y + a1.z * ad.z + a1.w * ad.w;
    float s2 = a2.x * as.x + a2.y * as.y + a2.z * as.z + a2.w * as.w;
    float d2 = a2.x * ad.x + a2.y * ad.y + a2.z * ad.z + a2.w * ad.w;
    float s3 = a3.x * as.x + a3.y * as.y + a3.z * as.z + a3.w * as.w;
    float d3 = a3.x * ad.x + a3.y * ad.y + a3.z * ad.z + a3.w * ad.w;
#pragma unroll
    for (int o = 2; o; o >>= 1) {
        s0 += __shfl_down_sync(0xffffffffu, s0, o, 4);
        d0 += __shfl_down_sync(0xffffffffu, d0, o, 4);
        s1 += __shfl_down_sync(0xffffffffu, s1, o, 4);
        d1 += __shfl_down_sync(0xffffffffu, d1, o, 4);
        s2 += __shfl_down_sync(0xffffffffu, s2, o, 4);
        d2 += __shfl_down_sync(0xffffffffu, d2, o, 4);
        s3 += __shfl_down_sync(0xffffffffu, s3, o, 4);
        d3 += __shfl_down_sync(0xffffffffu, d3, o, 4);
    }
    if ((sub & 3) == 0) {
        int head = sub >> 2;
        g_s1[(n0 + 0) * 2 + head] = s0;  g_d1[(n0 + 0) * 2 + head] = d0;
        g_s1[(n0 + 1) * 2 + head] = s1;  g_d1[(n0 + 1) * 2 + head] = d1;
        g_s1[(n0 + 2) * 2 + head] = s2;  g_d1[(n0 + 2) * 2 + head] = d2;
        g_s1[(n0 + 3) * 2 + head] = s3;  g_d1[(n0 + 3) * 2 + head] = d3;
    }
}

// ---------------- gather layer 1 + finalize + elu (warp / node, fp16 rows) ----
__global__ void k_gather1(const float* __restrict__ bias1) {
    int node = blockIdx.x * (blockDim.x >> 5) + (threadIdx.x >> 5);
    int lane = threadIdx.x & 31;
    if (node >= N_NODES) return;
    int beg = g_off[node];
    int n4  = (g_off[node + 1] - beg) >> 2;   // >= 1
    int head = lane >> 4;
    float dd = g_d1[node * 2 + head];
    float acc = 0.f, z = 0.f;

    const int4* ep = (const int4*)(g_esrc + beg);
    int4 sv = ep[0];
    for (int it = 0; it < n4; it++) {
        int4 nx = (it + 1 < n4) ? ep[it + 1] : sv;
        float l0 = g_s1[sv.x * 2 + head] + dd;
        float l1 = g_s1[sv.y * 2 + head] + dd;
        float l2 = g_s1[sv.z * 2 + head] + dd;
        float l3 = g_s1[sv.w * 2 + head] + dd;
        float h0 = __half2float(g_h1h[sv.x * D1 + lane]);
        float h1 = __half2float(g_h1h[sv.y * D1 + lane]);
        float h2 = __half2float(g_h1h[sv.z * D1 + lane]);
        float h3 = __half2float(g_h1h[sv.w * D1 + lane]);
        l0 = (l0 >= 0.f) ? l0 : SLOPE * l0;
        l1 = (l1 >= 0.f) ? l1 : SLOPE * l1;
        l2 = (l2 >= 0.f) ? l2 : SLOPE * l2;
        l3 = (l3 >= 0.f) ? l3 : SLOPE * l3;
        float x0 = __expf(l0), x1 = __expf(l1), x2 = __expf(l2), x3 = __expf(l3);
        acc += h0 * x0 + h1 * x1 + h2 * x2 + h3 * x3;
        z   += (x0 + x1) + (x2 + x3);
        sv = nx;
    }
    float v = acc / (z + 1e-16f) + bias1[lane];
    g_h1e[node * D1 + lane] = (v > 0.f) ? v : expm1f(v);
}

// ---------------- gemm2 + sd2 fused (16 threads / node pair) ------------------
__global__ void k_gemm2(const float* __restrict__ W2,
                        const float* __restrict__ a_src, const float* __restrict__ a_dst) {
    __shared__ float4 Ws4[D1 * (D2 / 4)];   // 8 KB
    for (int i = threadIdx.x; i < D1 * (D2 / 4); i += blockDim.x)
        Ws4[i] = ((const float4*)W2)[i];
    __syncthreads();

    int tid  = blockIdx.x * blockDim.x + threadIdx.x;
    int pair = tid >> 4;
    int sub  = tid & 15;
    if (pair >= N_NODES / 2) return;
    int n0 = pair * 2, n1 = n0 + 1;

    const float4* hr0 = (const float4*)(g_h1e + n0 * D1);
    const float4* hr1 = (const float4*)(g_h1e + n1 * D1);
    float4 acc0 = make_float4(0.f, 0.f, 0.f, 0.f);
    float4 acc1 = make_float4(0.f, 0.f, 0.f, 0.f);
#pragma unroll
    for (int k4 = 0; k4 < 8; k4++) {
        float4 xa = hr0[k4];
        float4 xb = hr1[k4];
        float4 w0 = Ws4[(k4 * 4 + 0) * 16 + sub];
        float4 w1 = Ws4[(k4 * 4 + 1) * 16 + sub];
        float4 w2 = Ws4[(k4 * 4 + 2) * 16 + sub];
        float4 w3 = Ws4[(k4 * 4 + 3) * 16 + sub];
        acc0.x += xa.x * w0.x + xa.y * w1.x + xa.z * w2.x + xa.w * w3.x;
        acc0.y += xa.x * w0.y + xa.y * w1.y + xa.z * w2.y + xa.w * w3.y;
        acc0.z += xa.x * w0.z + xa.y * w1.z + xa.z * w2.z + xa.w * w3.z;
        acc0.w += xa.x * w0.w + xa.y * w1.w + xa.z * w2.w + xa.w * w3.w;
        acc1.x += xb.x * w0.x + xb.y * w1.x + xb.z * w2.x + xb.w * w3.x;
        acc1.y += xb.x * w0.y + xb.y * w1.y + xb.z * w2.y + xb.w * w3.y;
        acc1.z += xb.x * w0.z + xb.y * w1.z + xb.z * w2.z + xb.w * w3.z;
        acc1.w += xb.x * w0.w + xb.y * w1.w + xb.z * w2.w + xb.w * w3.w;
    }
    g_h2h[n0 * 32 + sub * 2]     = __floats2half2_rn(acc0.x, acc0.y);
    g_h2h[n0 * 32 + sub * 2 + 1] = __floats2half2_rn(acc0.z, acc0.w);
    g_h2h[n1 * 32 + sub * 2]     = __floats2half2_rn(acc1.x, acc1.y);
    g_h2h[n1 * 32 + sub * 2 + 1] = __floats2half2_rn(acc1.z, acc1.w);

    float4 as = ((const float4*)a_src)[sub];
    float4 ad = ((const float4*)a_dst)[sub];
    float s0 = acc0.x * as.x + acc0.y * as.y + acc0.z * as.z + acc0.w * as.w;
    float d0 = acc0.x * ad.x + acc0.y * ad.y + acc0.z * ad.z + acc0.w * ad.w;
    float s1 = acc1.x * as.x + acc1.y * as.y + acc1.z * as.z + acc1.w * as.w;
    float d1 = acc1.x * ad.x + acc1.y * ad.y + acc1.z * ad.z + acc1.w * ad.w;
#pragma unroll
    for (int o = 8; o; o >>= 1) {
        s0 += __shfl_down_sync(0xffffffffu, s0, o, 16);
        d0 += __shfl_down_sync(0xffffffffu, d0, o, 16);
        s1 += __shfl_down_sync(0xffffffffu, s1, o, 16);
        d1 += __shfl_down_sync(0xffffffffu, d1, o, 16);
    }
    if (sub == 0) {
        g_s2[n0] = s0;
        g_d2[n0] = d0;
        g_s2[n1] = s1;
        g_d2[n1] = d1;
    }
}

// ---------------- gather layer 2 (warp / node, half2 lanes) -------------------
__global__ void k_gather2(const float* __restrict__ bias2, float* __restrict__ out) {
    int node = blockIdx.x * (blockDim.x >> 5) + (threadIdx.x >> 5);
    int lane = threadIdx.x & 31;
    if (node >= N_NODES) return;
    int beg = g_off[node];
    int n4  = (g_off[node + 1] - beg) >> 2;
    float dd = g_d2[node];
    float ax = 0.f, ay = 0.f, z = 0.f;

    const int4* ep = (const int4*)(g_esrc + beg);
    int4 sv = ep[0];
    for (int it = 0; it < n4; it++) {
        int4 nx = (it + 1 < n4) ? ep[it + 1] : sv;
        float l0 = g_s2[sv.x] + dd;
        float l1 = g_s2[sv.y] + dd;
        float l2 = g_s2[sv.z] + dd;
        float l3 = g_s2[sv.w] + dd;
        float2 h0 = __half22float2(g_h2h[sv.x * 32 + lane]);
        float2 h1 = __half22float2(g_h2h[sv.y * 32 + lane]);
        float2 h2 = __half22float2(g_h2h[sv.z * 32 + lane]);
        float2 h3 = __half22float2(g_h2h[sv.w * 32 + lane]);
        l0 = (l0 >= 0.f) ? l0 : SLOPE * l0;
        l1 = (l1 >= 0.f) ? l1 : SLOPE * l1;
        l2 = (l2 >= 0.f) ? l2 : SLOPE * l2;
        l3 = (l3 >= 0.f) ? l3 : SLOPE * l3;
        float x0 = __expf(l0), x1 = __expf(l1), x2 = __expf(l2), x3 = __expf(l3);
        ax += h0.x * x0 + h1.x * x1 + h2.x * x2 + h3.x * x3;
        ay += h0.y * x0 + h1.y * x1 + h2.y * x2 + h3.y * x3;
        z  += (x0 + x1) + (x2 + x3);
        sv = nx;
    }
    float inv = 1.f / (z + 1e-16f);
    float2 o2;
    o2.x = ax * inv + bias2[lane * 2];
    o2.y = ay * inv + bias2[lane * 2 + 1];
    *(float2*)(out + node * D2 + lane * 2) = o2;
}

extern "C" void kernel_launch(void* const* d_in, const int* in_sizes, int n_in,
                              void* d_out, int out_size) {
    const float* x     = (const float*)d_in[0];
    const int*   ei32  = (const int*)d_in[1];
    const float* W1    = (const float*)d_in[2];
    const float* asrc1 = (const float*)d_in[3];
    const float* adst1 = (const float*)d_in[4];
    const float* bias1 = (const float*)d_in[5];
    const float* W2    = (const float*)d_in[6];
    const float* asrc2 = (const float*)d_in[7];
    const float* adst2 = (const float*)d_in[8];
    const float* bias2 = (const float*)d_in[9];
    float* out = (float*)d_out;

    const int T = 256;

    static cudaStream_t s2 = nullptr;
    static cudaEvent_t  evF = nullptr, evJ = nullptr;
    if (!s2) {
        cudaStreamCreateWithFlags(&s2, cudaStreamNonBlocking);
        cudaEventCreateWithFlags(&evF, cudaEventDisableTiming);
        cudaEventCreateWithFlags(&evJ, cudaEventDisableTiming);
    }

    cudaEventRecord(evF, 0);
    cudaStreamWaitEvent(s2, evF, 0);

    k_gemm1<<<((N_NODES / 4) * 8 + T - 1) / T, T, 0, s2>>>(x, W1, asrc1, adst1); // 1 (s2)
    cudaEventRecord(evJ, s2);
    k_init<<<1024, T>>>(ei32);                                              // 2
    k_hist<<<((ET + 3) / 4 + T - 1) / T, T>>>(ei32);                        // 3
    k_scanA<<<SCAN_BLKS, 256>>>();                                           // 4 <- profiled
    k_scanB<<<1, 256>>>();                                                   // 5
    k_scanC<<<SCAN_BLKS, 256>>>();                                           // 6
    k_scatter<<<((ET + 3) / 4 + T - 1) / T, T>>>(ei32);                      // 7

    cudaStreamWaitEvent(0, evJ, 0);
    k_gather1<<<(N_NODES + 7) / 8, T>>>(bias1);                              // 8
    k_gemm2<<<((N_NODES / 2) * 16 + T - 1) / T, T>>>(W2, asrc2, adst2);      // 9
    k_gather2<<<(N_NODES + 7) / 8, T>>>(bias2, out);                         // 10
}

// round 15
// speedup vs baseline: 2.2321x; 1.0203x over previous
#include <cuda_runtime.h>
#include <cuda_fp16.h>

#define N_NODES 50000
#define N_EDGES 800000
#define ET (N_EDGES + N_NODES)        // edges + self loops
#define ESRC_SZ (ET + 3 * N_NODES)    // padded CSR capacity
#define IN_DIM 128
#define D1 32
#define D2 64
#define SLOPE 0.2f
#define SENT N_NODES                  // sentinel node id
#define SCAN_BLKS ((N_NODES + 255) / 256)   // 196

// ---------------- scratch ----------------
__device__ __align__(16) __half  g_h1h[(N_NODES + 1) * D1];  // x@W1, fp16 (+sentinel=0)
__device__ float g_s1[(N_NODES + 1) * 2];                    // sentinel = -1e30
__device__ float g_d1[N_NODES * 2];
__device__ __align__(16) float g_h1e[N_NODES * D1];          // elu(gat1 out), fp32
__device__ __align__(16) __half2 g_h2h[(N_NODES + 1) * 32];  // layer2 feats fp16 (+sent=0)
__device__ float g_s2[N_NODES + 1];                          // sentinel = -1e30
__device__ float g_d2[N_NODES];
__device__ int   g_deg[N_NODES];          // zero at load; re-zeroed by k_scanC each run
__device__ int   g_off[N_NODES + 1];
__device__ int   g_cur[N_NODES];
__device__ int   g_tmpoff[N_NODES];       // within-block exclusive prefix
__device__ int   g_bsum[SCAN_BLKS];       // per-block totals
__device__ int   g_bpre[256];             // exclusive prefix of block totals
__device__ __align__(16) int g_esrc[ESRC_SZ];                // CSR (pads sentinel-filled by scanC)
__device__ int   g_is64;

// ---------------- detect dtype + sentinel rows/scores (1 block, tiny) ---------
__global__ void k_detect(const int* __restrict__ ei32) {
    int t = threadIdx.x;
    if (t < D1) g_h1h[SENT * D1 + t] = __float2half(0.f);
    if (t < 32) g_h2h[SENT * 32 + t] = __floats2half2_rn(0.f, 0.f);
    if (t == 0) {
        int odd_nonzero = 0;
#pragma unroll
        for (int j = 1; j < 128; j += 2) odd_nonzero |= (ei32[j] != 0);
        g_is64 = odd_nonzero ? 0 : 1;
        g_s1[2 * SENT] = -1e30f;
        g_s1[2 * SENT + 1] = -1e30f;
        g_s2[SENT] = -1e30f;
    }
}

// ---------------- histogram of dst degrees (4 edges / thread) -----------------
__global__ void k_hist(const int* __restrict__ ei32) {
    int base = (blockIdx.x * blockDim.x + threadIdx.x) * 4;
    int is64 = g_is64;
#pragma unroll
    for (int k = 0; k < 4; k++) {
        int i = base + k;
        if (i >= ET) return;
        int dst;
        if (i < N_EDGES) dst = is64 ? ei32[2 * (N_EDGES + i)] : ei32[N_EDGES + i];
        else             dst = i - N_EDGES;
        atomicAdd(&g_deg[dst], 1);
    }
}

// ---------------- 3-phase decoupled scan of padded degrees --------------------
__global__ void k_scanA() {
    __shared__ int sh[256];
    int i = blockIdx.x * 256 + threadIdx.x;
    int v = (i < N_NODES) ? ((g_deg[i] + 3) & ~3) : 0;
    int incl = v;
#pragma unroll
    for (int off = 1; off < 256; off <<= 1) {
        sh[threadIdx.x] = incl;
        __syncthreads();
        int add = (threadIdx.x >= off) ? sh[threadIdx.x - off] : 0;
        __syncthreads();
        incl += add;
    }
    if (i < N_NODES) g_tmpoff[i] = incl - v;
    if (threadIdx.x == 255) g_bsum[blockIdx.x] = incl;
}

__global__ void k_scanB() {
    __shared__ int sh[256];
    int t = threadIdx.x;
    int v = (t < SCAN_BLKS) ? g_bsum[t] : 0;
    int incl = v;
#pragma unroll
    for (int off = 1; off < 256; off <<= 1) {
        sh[t] = incl;
        __syncthreads();
        int add = (t >= off) ? sh[t - off] : 0;
        __syncthreads();
        incl += add;
    }
    g_bpre[t] = incl - v;
    if (t == SCAN_BLKS - 1) g_off[N_NODES] = incl;   // total padded size
}

// scanC: final offsets, sentinel-fill pad slots, re-zero deg for next replay
__global__ void k_scanC() {
    int i = blockIdx.x * 256 + threadIdx.x;
    if (i >= N_NODES) return;
    int off = g_tmpoff[i] + g_bpre[blockIdx.x];
    int d   = g_deg[i];
    g_off[i] = off;
    g_cur[i] = off;
    int pend = off + ((d + 3) & ~3);
    for (int p = off + d; p < pend; p++) g_esrc[p] = SENT;
    g_deg[i] = 0;
}

// ---------------- scatter src indices into CSR buckets (8 / thread) -----------
__global__ void k_scatter(const int* __restrict__ ei32) {
    int base = (blockIdx.x * blockDim.x + threadIdx.x) * 8;
    int is64 = g_is64;
#pragma unroll
    for (int k = 0; k < 8; k++) {
        int i = base + k;
        if (i >= ET) return;
        int src, dst;
        if (i < N_EDGES) {
            if (is64) { src = ei32[2 * i]; dst = ei32[2 * (N_EDGES + i)]; }
            else      { src = ei32[i];     dst = ei32[N_EDGES + i]; }
        } else {
            src = dst = i - N_EDGES;
        }
        int pos = atomicAdd(&g_cur[dst], 1);
        g_esrc[pos] = src;
    }
}

// ---------------- gemm1 + sd1 fused (8 threads / node QUAD, 4 cols x 4 nodes) --
__global__ void __launch_bounds__(256) k_gemm1(
        const float* __restrict__ x, const float* __restrict__ W1,
        const float* __restrict__ a_src, const float* __restrict__ a_dst) {
    __shared__ float4 Ws4[IN_DIM * (D1 / 4)];   // 16 KB
    for (int i = threadIdx.x; i < IN_DIM * (D1 / 4); i += blockDim.x)
        Ws4[i] = ((const float4*)W1)[i];
    __syncthreads();

    int tid  = blockIdx.x * blockDim.x + threadIdx.x;
    int quad = tid >> 3;
    int sub  = tid & 7;
    if (quad >= N_NODES / 4) return;   // 50000 % 4 == 0
    int n0 = quad * 4;

    const float4* x0p = (const float4*)(x + (n0 + 0) * IN_DIM);
    const float4* x1p = (const float4*)(x + (n0 + 1) * IN_DIM);
    const float4* x2p = (const float4*)(x + (n0 + 2) * IN_DIM);
    const float4* x3p = (const float4*)(x + (n0 + 3) * IN_DIM);
    float4 a0 = make_float4(0.f, 0.f, 0.f, 0.f);
    float4 a1 = a0, a2 = a0, a3 = a0;
#pragma unroll 2
    for (int k4 = 0; k4 < 32; k4++) {
        float4 w0 = Ws4[(k4 * 4 + 0) * 8 + sub];
        float4 w1 = Ws4[(k4 * 4 + 1) * 8 + sub];
        float4 w2 = Ws4[(k4 * 4 + 2) * 8 + sub];
        float4 w3 = Ws4[(k4 * 4 + 3) * 8 + sub];
        float4 xv;
        xv = x0p[k4];
        a0.x += xv.x * w0.x + xv.y * w1.x + xv.z * w2.x + xv.w * w3.x;
        a0.y += xv.x * w0.y + xv.y * w1.y + xv.z * w2.y + xv.w * w3.y;
        a0.z += xv.x * w0.z + xv.y * w1.z + xv.z * w2.z + xv.w * w3.z;
        a0.w += xv.x * w0.w + xv.y * w1.w + xv.z * w2.w + xv.w * w3.w;
        xv = x1p[k4];
        a1.x += xv.x * w0.x + xv.y * w1.x + xv.z * w2.x + xv.w * w3.x;
        a1.y += xv.x * w0.y + xv.y * w1.y + xv.z * w2.y + xv.w * w3.y;
        a1.z += xv.x * w0.z + xv.y * w1.z + xv.z * w2.z + xv.w * w3.z;
        a1.w += xv.x * w0.w + xv.y * w1.w + xv.z * w2.w + xv.w * w3.w;
        xv = x2p[k4];
        a2.x += xv.x * w0.x + xv.y * w1.x + xv.z * w2.x + xv.w * w3.x;
        a2.y += xv.x * w0.y + xv.y * w1.y + xv.z * w2.y + xv.w * w3.y;
        a2.z += xv.x * w0.z + xv.y * w1.z + xv.z * w2.z + xv.w * w3.z;
        a2.w += xv.x * w0.w + xv.y * w1.w + xv.z * w2.w + xv.w * w3.w;
        xv = x3p[k4];
        a3.x += xv.x * w0.x + xv.y * w1.x + xv.z * w2.x + xv.w * w3.x;
        a3.y += xv.x * w0.y + xv.y * w1.y + xv.z * w2.y + xv.w * w3.y;
        a3.z += xv.x * w0.z + xv.y * w1.z + xv.z * w2.z + xv.w * w3.z;
        a3.w += xv.x * w0.w + xv.y * w1.w + xv.z * w2.w + xv.w * w3.w;
    }
    __half2* h1p = (__half2*)g_h1h;
    h1p[(n0 + 0) * 16 + sub * 2]     = __floats2half2_rn(a0.x, a0.y);
    h1p[(n0 + 0) * 16 + sub * 2 + 1] = __floats2half2_rn(a0.z, a0.w);
    h1p[(n0 + 1) * 16 + sub * 2]     = __floats2half2_rn(a1.x, a1.y);
    h1p[(n0 + 1) * 16 + sub * 2 + 1] = __floats2half2_rn(a1.z, a1.w);
    h1p[(n0 + 2) * 16 + sub * 2]     = __floats2half2_rn(a2.x, a2.y);
    h1p[(n0 + 2) * 16 + sub * 2 + 1] = __floats2half2_rn(a2.z, a2.w);
    h1p[(n0 + 3) * 16 + sub * 2]     = __floats2half2_rn(a3.x, a3.y);
    h1p[(n0 + 3) * 16 + sub * 2 + 1] = __floats2half2_rn(a3.z, a3.w);

    float4 as = ((const float4*)a_src)[sub];
    float4 ad = ((const float4*)a_dst)[sub];
    float s0 = a0.x * as.x + a0.y * as.y + a0.z * as.z + a0.w * as.w;
    float d0 = a0.x * ad.x + a0.y * ad.y + a0.z * ad.z + a0.w * ad.w;
    float s1 = a1.x * as.x + a1.y * as.y + a1.z * as.z + a1.w * as.w;
    float d1 = a1.x * ad.x + a1.y * ad.y + a1.z * ad.z + a1.w * ad.w;
    float s2 = a2.x * as.x + a2.y * as.y + a2.z * as.z + a2.w * as.w;
    float d2 = a2.x * ad.x + a2.y * ad.y + a2.z * ad.z + a2.w * ad.w;
    float s3 = a3.x * as.x + a3.y * as.y + a3.z * as.z + a3.w * as.w;
    float d3 = a3.x * ad.x + a3.y * ad.y + a3.z * ad.z + a3.w * ad.w;
#pragma unroll
    for (int o = 2; o; o >>= 1) {
        s0 += __shfl_down_sync(0xffffffffu, s0, o, 4);
        d0 += __shfl_down_sync(0xffffffffu, d0, o, 4);
        s1 += __shfl_down_sync(0xffffffffu, s1, o, 4);
        d1 += __shfl_down_sync(0xffffffffu, d1, o, 4);
        s2 += __shfl_down_sync(0xffffffffu, s2, o, 4);
        d2 += __shfl_down_sync(0xffffffffu, d2, o, 4);
        s3 += __shfl_down_sync(0xffffffffu, s3, o, 4);
        d3 += __shfl_down_sync(0xffffffffu, d3, o, 4);
    }
    if ((sub & 3) == 0) {
        int head = sub >> 2;
        g_s1[(n0 + 0) * 2 + head] = s0;  g_d1[(n0 + 0) * 2 + head] = d0;
        g_s1[(n0 + 1) * 2 + head] = s1;  g_d1[(n0 + 1) * 2 + head] = d1;
        g_s1[(n0 + 2) * 2 + head] = s2;  g_d1[(n0 + 2) * 2 + head] = d2;
        g_s1[(n0 + 3) * 2 + head] = s3;  g_d1[(n0 + 3) * 2 + head] = d3;
    }
}

// ---------------- gather layer 1 + finalize + elu (warp / node, fp16 rows) ----
__global__ void k_gather1(const float* __restrict__ bias1) {
    int node = blockIdx.x * (blockDim.x >> 5) + (threadIdx.x >> 5);
    int lane = threadIdx.x & 31;
    if (node >= N_NODES) return;
    int beg = g_off[node];
    int n4  = (g_off[node + 1] - beg) >> 2;   // >= 1
    int head = lane >> 4;
    float dd = g_d1[node * 2 + head];
    float acc = 0.f, z = 0.f;

    const int4* ep = (const int4*)(g_esrc + beg);
    int4 sv = ep[0];
    for (int it = 0; it < n4; it++) {
        int4 nx = (it + 1 < n4) ? ep[it + 1] : sv;
        float l0 = g_s1[sv.x * 2 + head] + dd;
        float l1 = g_s1[sv.y * 2 + head] + dd;
        float l2 = g_s1[sv.z * 2 + head] + dd;
        float l3 = g_s1[sv.w * 2 + head] + dd;
        float h0 = __half2float(g_h1h[sv.x * D1 + lane]);
        float h1 = __half2float(g_h1h[sv.y * D1 + lane]);
        float h2 = __half2float(g_h1h[sv.z * D1 + lane]);
        float h3 = __half2float(g_h1h[sv.w * D1 + lane]);
        l0 = (l0 >= 0.f) ? l0 : SLOPE * l0;
        l1 = (l1 >= 0.f) ? l1 : SLOPE * l1;
        l2 = (l2 >= 0.f) ? l2 : SLOPE * l2;
        l3 = (l3 >= 0.f) ? l3 : SLOPE * l3;
        float x0 = __expf(l0), x1 = __expf(l1), x2 = __expf(l2), x3 = __expf(l3);
        acc += h0 * x0 + h1 * x1 + h2 * x2 + h3 * x3;
        z   += (x0 + x1) + (x2 + x3);
        sv = nx;
    }
    float v = acc / (z + 1e-16f) + bias1[lane];
    g_h1e[node * D1 + lane] = (v > 0.f) ? v : expm1f(v);
}

// ---------------- gemm2 + sd2 fused (16 threads / node pair) ------------------
__global__ void k_gemm2(const float* __restrict__ W2,
                        const float* __restrict__ a_src, const float* __restrict__ a_dst) {
    __shared__ float4 Ws4[D1 * (D2 / 4)];   // 8 KB
    for (int i = threadIdx.x; i < D1 * (D2 / 4); i += blockDim.x)
        Ws4[i] = ((const float4*)W2)[i];
    __syncthreads();

    int tid  = blockIdx.x * blockDim.x + threadIdx.x;
    int pair = tid >> 4;
    int sub  = tid & 15;
    if (pair >= N_NODES / 2) return;
    int n0 = pair * 2, n1 = n0 + 1;

    const float4* hr0 = (const float4*)(g_h1e + n0 * D1);
    const float4* hr1 = (const float4*)(g_h1e + n1 * D1);
    float4 acc0 = make_float4(0.f, 0.f, 0.f, 0.f);
    float4 acc1 = make_float4(0.f, 0.f, 0.f, 0.f);
#pragma unroll
    for (int k4 = 0; k4 < 8; k4++) {
        float4 xa = hr0[k4];
        float4 xb = hr1[k4];
        float4 w0 = Ws4[(k4 * 4 + 0) * 16 + sub];
        float4 w1 = Ws4[(k4 * 4 + 1) * 16 + sub];
        float4 w2 = Ws4[(k4 * 4 + 2) * 16 + sub];
        float4 w3 = Ws4[(k4 * 4 + 3) * 16 + sub];
        acc0.x += xa.x * w0.x + xa.y * w1.x + xa.z * w2.x + xa.w * w3.x;
        acc0.y += xa.x * w0.y + xa.y * w1.y + xa.z * w2.y + xa.w * w3.y;
        acc0.z += xa.x * w0.z + xa.y * w1.z + xa.z * w2.z + xa.w * w3.z;
        acc0.w += xa.x * w0.w + xa.y * w1.w + xa.z * w2.w + xa.w * w3.w;
        acc1.x += xb.x * w0.x + xb.y * w1.x + xb.z * w2.x + xb.w * w3.x;
        acc1.y += xb.x * w0.y + xb.y * w1.y + xb.z * w2.y + xb.w * w3.y;
        acc1.z += xb.x * w0.z + xb.y * w1.z + xb.z * w2.z + xb.w * w3.z;
        acc1.w += xb.x * w0.w + xb.y * w1.w + xb.z * w2.w + xb.w * w3.w;
    }
    g_h2h[n0 * 32 + sub * 2]     = __floats2half2_rn(acc0.x, acc0.y);
    g_h2h[n0 * 32 + sub * 2 + 1] = __floats2half2_rn(acc0.z, acc0.w);
    g_h2h[n1 * 32 + sub * 2]     = __floats2half2_rn(acc1.x, acc1.y);
    g_h2h[n1 * 32 + sub * 2 + 1] = __floats2half2_rn(acc1.z, acc1.w);

    float4 as = ((const float4*)a_src)[sub];
    float4 ad = ((const float4*)a_dst)[sub];
    float s0 = acc0.x * as.x + acc0.y * as.y + acc0.z * as.z + acc0.w * as.w;
    float d0 = acc0.x * ad.x + acc0.y * ad.y + acc0.z * ad.z + acc0.w * ad.w;
    float s1 = acc1.x * as.x + acc1.y * as.y + acc1.z * as.z + acc1.w * as.w;
    float d1 = acc1.x * ad.x + acc1.y * ad.y + acc1.z * ad.z + acc1.w * ad.w;
#pragma unroll
    for (int o = 8; o; o >>= 1) {
        s0 += __shfl_down_sync(0xffffffffu, s0, o, 16);
        d0 += __shfl_down_sync(0xffffffffu, d0, o, 16);
        s1 += __shfl_down_sync(0xffffffffu, s1, o, 16);
        d1 += __shfl_down_sync(0xffffffffu, d1, o, 16);
    }
    if (sub == 0) {
        g_s2[n0] = s0;
        g_d2[n0] = d0;
        g_s2[n1] = s1;
        g_d2[n1] = d1;
    }
}

// ---------------- gather layer 2 (warp / node, half2 lanes) -------------------
__global__ void k_gather2(const float* __restrict__ bias2, float* __restrict__ out) {
    int node = blockIdx.x * (blockDim.x >> 5) + (threadIdx.x >> 5);
    int lane = threadIdx.x & 31;
    if (node >= N_NODES) return;
    int beg = g_off[node];
    int n4  = (g_off[node + 1] - beg) >> 2;
    float dd = g_d2[node];
    float ax = 0.f, ay = 0.f, z = 0.f;

    const int4* ep = (const int4*)(g_esrc + beg);
    int4 sv = ep[0];
    for (int it = 0; it < n4; it++) {
        int4 nx = (it + 1 < n4) ? ep[it + 1] : sv;
        float l0 = g_s2[sv.x] + dd;
        float l1 = g_s2[sv.y] + dd;
        float l2 = g_s2[sv.z] + dd;
        float l3 = g_s2[sv.w] + dd;
        float2 h0 = __half22float2(g_h2h[sv.x * 32 + lane]);
        float2 h1 = __half22float2(g_h2h[sv.y * 32 + lane]);
        float2 h2 = __half22float2(g_h2h[sv.z * 32 + lane]);
        float2 h3 = __half22float2(g_h2h[sv.w * 32 + lane]);
        l0 = (l0 >= 0.f) ? l0 : SLOPE * l0;
        l1 = (l1 >= 0.f) ? l1 : SLOPE * l1;
        l2 = (l2 >= 0.f) ? l2 : SLOPE * l2;
        l3 = (l3 >= 0.f) ? l3 : SLOPE * l3;
        float x0 = __expf(l0), x1 = __expf(l1), x2 = __expf(l2), x3 = __expf(l3);
        ax += h0.x * x0 + h1.x * x1 + h2.x * x2 + h3.x * x3;
        ay += h0.y * x0 + h1.y * x1 + h2.y * x2 + h3.y * x3;
        z  += (x0 + x1) + (x2 + x3);
        sv = nx;
    }
    float inv = 1.f / (z + 1e-16f);
    float2 o2;
    o2.x = ax * inv + bias2[lane * 2];
    o2.y = ay * inv + bias2[lane * 2 + 1];
    *(float2*)(out + node * D2 + lane * 2) = o2;
}

extern "C" void kernel_launch(void* const* d_in, const int* in_sizes, int n_in,
                              void* d_out, int out_size) {
    const float* x     = (const float*)d_in[0];
    const int*   ei32  = (const int*)d_in[1];
    const float* W1    = (const float*)d_in[2];
    const float* asrc1 = (const float*)d_in[3];
    const float* adst1 = (const float*)d_in[4];
    const float* bias1 = (const float*)d_in[5];
    const float* W2    = (const float*)d_in[6];
    const float* asrc2 = (const float*)d_in[7];
    const float* adst2 = (const float*)d_in[8];
    const float* bias2 = (const float*)d_in[9];
    float* out = (float*)d_out;

    const int T = 256;

    static cudaStream_t s2 = nullptr;
    static cudaEvent_t  evF = nullptr, evJ = nullptr;
    if (!s2) {
        cudaStreamCreateWithFlags(&s2, cudaStreamNonBlocking);
        cudaEventCreateWithFlags(&evF, cudaEventDisableTiming);
        cudaEventCreateWithFlags(&evJ, cudaEventDisableTiming);
    }

    cudaEventRecord(evF, 0);
    cudaStreamWaitEvent(s2, evF, 0);

    k_gemm1<<<((N_NODES / 4) * 8 + T - 1) / T, T, 0, s2>>>(x, W1, asrc1, adst1); // 1 (s2)
    cudaEventRecord(evJ, s2);
    k_detect<<<1, 64>>>(ei32);                                               // 2
    k_hist<<<((ET + 3) / 4 + T - 1) / T, T>>>(ei32);                         // 3
    k_scanA<<<SCAN_BLKS, 256>>>();                                            // 4 <- profiled
    k_scanB<<<1, 256>>>();                                                    // 5
    k_scanC<<<SCAN_BLKS, 256>>>();                                            // 6
    k_scatter<<<((ET + 7) / 8 + T - 1) / T, T>>>(ei32);                       // 7

    cudaStreamWaitEvent(0, evJ, 0);
    k_gather1<<<(N_NODES + 7) / 8, T>>>(bias1);                               // 8
    k_gemm2<<<((N_NODES / 2) * 16 + T - 1) / T, T>>>(W2, asrc2, adst2);       // 9
    k_gather2<<<(N_NODES + 7) / 8, T>>>(bias2, out);                          // 10
}

// round 16
// speedup vs baseline: 2.2816x; 1.0222x over previous
#include <cuda_runtime.h>
#include <cuda_fp16.h>

#define N_NODES 50000
#define N_EDGES 800000
#define ET (N_EDGES + N_NODES)        // edges + self loops
#define ESRC_SZ (ET + 3 * N_NODES)    // padded CSR capacity
#define IN_DIM 128
#define D1 32
#define D2 64
#define SLOPE 0.2f
#define SENT N_NODES                  // sentinel node id
#define SCAN_BLKS ((N_NODES + 255) / 256)   // 196

// ---------------- scratch ----------------
__device__ __align__(16) __half  g_h1h[(N_NODES + 1) * D1];  // x@W1, fp16 (+sentinel=0)
__device__ float g_s1[(N_NODES + 1) * 2];                    // sentinel = -1e30
__device__ float g_d1[N_NODES * 2];
__device__ __align__(16) __half2 g_h2h[(N_NODES + 1) * 32];  // layer2 feats fp16, packed {c, c+32}
__device__ float g_s2[N_NODES + 1];                          // sentinel = -1e30
__device__ float g_d2[N_NODES];
__device__ int   g_deg[N_NODES];          // zero at load; re-zeroed by k_scanC each run
__device__ int   g_off[N_NODES + 1];
__device__ int   g_cur[N_NODES];
__device__ int   g_tmpoff[N_NODES];       // within-block exclusive prefix
__device__ int   g_bsum[SCAN_BLKS];       // per-block totals
__device__ int   g_bpre[256];             // exclusive prefix of block totals
__device__ __align__(16) int g_esrc[ESRC_SZ];                // CSR (pads sentinel-filled by scanC)

__device__ __forceinline__ int detect64(const int* ei32) {
    // int64 LE with values < 2^31 => odd 32-bit words are 0.
    return ((ei32[1] | ei32[3] | ei32[5] | ei32[7]) == 0) ? 1 : 0;
}

// ---------------- histogram of dst degrees (4 edges / thread) -----------------
__global__ void k_hist(const int* __restrict__ ei32) {
    int base = (blockIdx.x * blockDim.x + threadIdx.x) * 4;
    int is64 = detect64(ei32);
#pragma unroll
    for (int k = 0; k < 4; k++) {
        int i = base + k;
        if (i >= ET) return;
        int dst;
        if (i < N_EDGES) dst = is64 ? ei32[2 * (N_EDGES + i)] : ei32[N_EDGES + i];
        else             dst = i - N_EDGES;
        atomicAdd(&g_deg[dst], 1);
    }
}

// ---------------- 3-phase decoupled scan of padded degrees --------------------
__global__ void k_scanA() {
    __shared__ int sh[256];
    int i = blockIdx.x * 256 + threadIdx.x;
    int v = (i < N_NODES) ? ((g_deg[i] + 3) & ~3) : 0;
    int incl = v;
#pragma unroll
    for (int off = 1; off < 256; off <<= 1) {
        sh[threadIdx.x] = incl;
        __syncthreads();
        int add = (threadIdx.x >= off) ? sh[threadIdx.x - off] : 0;
        __syncthreads();
        incl += add;
    }
    if (i < N_NODES) g_tmpoff[i] = incl - v;
    if (threadIdx.x == 255) g_bsum[blockIdx.x] = incl;
}

// scanB: scan block totals; also writes sentinel rows/scores (absorbed k_detect)
__global__ void k_scanB() {
    __shared__ int sh[256];
    int t = threadIdx.x;
    int v = (t < SCAN_BLKS) ? g_bsum[t] : 0;
    int incl = v;
#pragma unroll
    for (int off = 1; off < 256; off <<= 1) {
        sh[t] = incl;
        __syncthreads();
        int add = (t >= off) ? sh[t - off] : 0;
        __syncthreads();
        incl += add;
    }
    g_bpre[t] = incl - v;
    if (t == SCAN_BLKS - 1) g_off[N_NODES] = incl;   // total padded size
    // sentinel rows & scores
    if (t < D1) g_h1h[SENT * D1 + t] = __float2half(0.f);
    if (t < 32) g_h2h[SENT * 32 + t] = __floats2half2_rn(0.f, 0.f);
    if (t == 0) {
        g_s1[2 * SENT] = -1e30f;
        g_s1[2 * SENT + 1] = -1e30f;
        g_s2[SENT] = -1e30f;
    }
}

// scanC: final offsets, sentinel-fill pad slots, re-zero deg for next replay
__global__ void k_scanC() {
    int i = blockIdx.x * 256 + threadIdx.x;
    if (i >= N_NODES) return;
    int off = g_tmpoff[i] + g_bpre[blockIdx.x];
    int d   = g_deg[i];
    g_off[i] = off;
    g_cur[i] = off;
    int pend = off + ((d + 3) & ~3);
    for (int p = off + d; p < pend; p++) g_esrc[p] = SENT;
    g_deg[i] = 0;
}

// ---------------- scatter src indices into CSR buckets (8 / thread) -----------
__global__ void k_scatter(const int* __restrict__ ei32) {
    int base = (blockIdx.x * blockDim.x + threadIdx.x) * 8;
    int is64 = detect64(ei32);
#pragma unroll
    for (int k = 0; k < 8; k++) {
        int i = base + k;
        if (i >= ET) return;
        int src, dst;
        if (i < N_EDGES) {
            if (is64) { src = ei32[2 * i]; dst = ei32[2 * (N_EDGES + i)]; }
            else      { src = ei32[i];     dst = ei32[N_EDGES + i]; }
        } else {
            src = dst = i - N_EDGES;
        }
        int pos = atomicAdd(&g_cur[dst], 1);
        g_esrc[pos] = src;
    }
}

// ---------------- gemm1 + sd1 fused (8 threads / node QUAD, 4 cols x 4 nodes) --
__global__ void __launch_bounds__(256) k_gemm1(
        const float* __restrict__ x, const float* __restrict__ W1,
        const float* __restrict__ a_src, const float* __restrict__ a_dst) {
    __shared__ float4 Ws4[IN_DIM * (D1 / 4)];   // 16 KB
    for (int i = threadIdx.x; i < IN_DIM * (D1 / 4); i += blockDim.x)
        Ws4[i] = ((const float4*)W1)[i];
    __syncthreads();

    int tid  = blockIdx.x * blockDim.x + threadIdx.x;
    int quad = tid >> 3;
    int sub  = tid & 7;
    if (quad >= N_NODES / 4) return;   // 50000 % 4 == 0
    int n0 = quad * 4;

    const float4* x0p = (const float4*)(x + (n0 + 0) * IN_DIM);
    const float4* x1p = (const float4*)(x + (n0 + 1) * IN_DIM);
    const float4* x2p = (const float4*)(x + (n0 + 2) * IN_DIM);
    const float4* x3p = (const float4*)(x + (n0 + 3) * IN_DIM);
    float4 a0 = make_float4(0.f, 0.f, 0.f, 0.f);
    float4 a1 = a0, a2 = a0, a3 = a0;
#pragma unroll 2
    for (int k4 = 0; k4 < 32; k4++) {
        float4 w0 = Ws4[(k4 * 4 + 0) * 8 + sub];
        float4 w1 = Ws4[(k4 * 4 + 1) * 8 + sub];
        float4 w2 = Ws4[(k4 * 4 + 2) * 8 + sub];
        float4 w3 = Ws4[(k4 * 4 + 3) * 8 + sub];
        float4 xv;
        xv = x0p[k4];
        a0.x += xv.x * w0.x + xv.y * w1.x + xv.z * w2.x + xv.w * w3.x;
        a0.y += xv.x * w0.y + xv.y * w1.y + xv.z * w2.y + xv.w * w3.y;
        a0.z += xv.x * w0.z + xv.y * w1.z + xv.z * w2.z + xv.w * w3.z;
        a0.w += xv.x * w0.w + xv.y * w1.w + xv.z * w2.w + xv.w * w3.w;
        xv = x1p[k4];
        a1.x += xv.x * w0.x + xv.y * w1.x + xv.z * w2.x + xv.w * w3.x;
        a1.y += xv.x * w0.y + xv.y * w1.y + xv.z * w2.y + xv.w * w3.y;
        a1.z += xv.x * w0.z + xv.y * w1.z + xv.z * w2.z + xv.w * w3.z;
        a1.w += xv.x * w0.w + xv.y * w1.w + xv.z * w2.w + xv.w * w3.w;
        xv = x2p[k4];
        a2.x += xv.x * w0.x + xv.y * w1.x + xv.z * w2.x + xv.w * w3.x;
        a2.y += xv.x * w0.y + xv.y * w1.y + xv.z * w2.y + xv.w * w3.y;
        a2.z += xv.x * w0.z + xv.y * w1.z + xv.z * w2.z + xv.w * w3.z;
        a2.w += xv.x * w0.w + xv.y * w1.w + xv.z * w2.w + xv.w * w3.w;
        xv = x3p[k4];
        a3.x += xv.x * w0.x + xv.y * w1.x + xv.z * w2.x + xv.w * w3.x;
        a3.y += xv.x * w0.y + xv.y * w1.y + xv.z * w2.y + xv.w * w3.y;
        a3.z += xv.x * w0.z + xv.y * w1.z + xv.z * w2.z + xv.w * w3.z;
        a3.w += xv.x * w0.w + xv.y * w1.w + xv.z * w2.w + xv.w * w3.w;
    }
    __half2* h1p = (__half2*)g_h1h;
    h1p[(n0 + 0) * 16 + sub * 2]     = __floats2half2_rn(a0.x, a0.y);
    h1p[(n0 + 0) * 16 + sub * 2 + 1] = __floats2half2_rn(a0.z, a0.w);
    h1p[(n0 + 1) * 16 + sub * 2]     = __floats2half2_rn(a1.x, a1.y);
    h1p[(n0 + 1) * 16 + sub * 2 + 1] = __floats2half2_rn(a1.z, a1.w);
    h1p[(n0 + 2) * 16 + sub * 2]     = __floats2half2_rn(a2.x, a2.y);
    h1p[(n0 + 2) * 16 + sub * 2 + 1] = __floats2half2_rn(a2.z, a2.w);
    h1p[(n0 + 3) * 16 + sub * 2]     = __floats2half2_rn(a3.x, a3.y);
    h1p[(n0 + 3) * 16 + sub * 2 + 1] = __floats2half2_rn(a3.z, a3.w);

    float4 as = ((const float4*)a_src)[sub];
    float4 ad = ((const float4*)a_dst)[sub];
    float s0 = a0.x * as.x + a0.y * as.y + a0.z * as.z + a0.w * as.w;
    float d0 = a0.x * ad.x + a0.y * ad.y + a0.z * ad.z + a0.w * ad.w;
    float s1 = a1.x * as.x + a1.y * as.y + a1.z * as.z + a1.w * as.w;
    float d1 = a1.x * ad.x + a1.y * ad.y + a1.z * ad.z + a1.w * ad.w;
    float s2 = a2.x * as.x + a2.y * as.y + a2.z * as.z + a2.w * as.w;
    float d2 = a2.x * ad.x + a2.y * ad.y + a2.z * ad.z + a2.w * ad.w;
    float s3 = a3.x * as.x + a3.y * as.y + a3.z * as.z + a3.w * as.w;
    float d3 = a3.x * ad.x + a3.y * ad.y + a3.z * ad.z + a3.w * ad.w;
#pragma unroll
    for (int o = 2; o; o >>= 1) {
        s0 += __shfl_down_sync(0xffffffffu, s0, o, 4);
        d0 += __shfl_down_sync(0xffffffffu, d0, o, 4);
        s1 += __shfl_down_sync(0xffffffffu, s1, o, 4);
        d1 += __shfl_down_sync(0xffffffffu, d1, o, 4);
        s2 += __shfl_down_sync(0xffffffffu, s2, o, 4);
        d2 += __shfl_down_sync(0xffffffffu, d2, o, 4);
        s3 += __shfl_down_sync(0xffffffffu, s3, o, 4);
        d3 += __shfl_down_sync(0xffffffffu, d3, o, 4);
    }
    if ((sub & 3) == 0) {
        int head = sub >> 2;
        g_s1[(n0 + 0) * 2 + head] = s0;  g_d1[(n0 + 0) * 2 + head] = d0;
        g_s1[(n0 + 1) * 2 + head] = s1;  g_d1[(n0 + 1) * 2 + head] = d1;
        g_s1[(n0 + 2) * 2 + head] = s2;  g_d1[(n0 + 2) * 2 + head] = d2;
        g_s1[(n0 + 3) * 2 + head] = s3;  g_d1[(n0 + 3) * 2 + head] = d3;
    }
}

// ---- layer1 fused: gather+elu (warp/node) then block-local gemm2+sd2 ---------
// Grid is exact: 6250 blocks x 8 warps = 50000 nodes. No early returns.
__global__ void __launch_bounds__(256) k_layer1(
        const float* __restrict__ bias1, const float* __restrict__ W2,
        const float* __restrict__ as2, const float* __restrict__ ad2) {
    __shared__ float  h1s[8 * D1];        // 1 KB: h1e rows of this block's 8 nodes
    __shared__ float2 W2p[D1 * 32];       // 8 KB: W2 packed as {col c, col c+32} per k

    for (int i = threadIdx.x; i < D1 * 32; i += 256) {
        int k = i >> 5, c = i & 31;
        W2p[i] = make_float2(W2[k * D2 + c], W2[k * D2 + 32 + c]);
    }
    __syncthreads();

    int wid  = threadIdx.x >> 5;
    int lane = threadIdx.x & 31;
    int node = blockIdx.x * 8 + wid;      // < N_NODES always
    int beg = g_off[node];
    int n4  = (g_off[node + 1] - beg) >> 2;   // >= 1
    int head = lane >> 4;
    float dd = g_d1[node * 2 + head];
    float acc = 0.f, z = 0.f;

    const int4* ep = (const int4*)(g_esrc + beg);
    int4 sv = ep[0];
    for (int it = 0; it < n4; it++) {
        int4 nx = (it + 1 < n4) ? ep[it + 1] : sv;
        float l0 = g_s1[sv.x * 2 + head] + dd;
        float l1 = g_s1[sv.y * 2 + head] + dd;
        float l2 = g_s1[sv.z * 2 + head] + dd;
        float l3 = g_s1[sv.w * 2 + head] + dd;
        float h0 = __half2float(g_h1h[sv.x * D1 + lane]);
        float h1 = __half2float(g_h1h[sv.y * D1 + lane]);
        float h2 = __half2float(g_h1h[sv.z * D1 + lane]);
        float h3 = __half2float(g_h1h[sv.w * D1 + lane]);
        l0 = (l0 >= 0.f) ? l0 : SLOPE * l0;
        l1 = (l1 >= 0.f) ? l1 : SLOPE * l1;
        l2 = (l2 >= 0.f) ? l2 : SLOPE * l2;
        l3 = (l3 >= 0.f) ? l3 : SLOPE * l3;
        float x0 = __expf(l0), x1 = __expf(l1), x2 = __expf(l2), x3 = __expf(l3);
        acc += h0 * x0 + h1 * x1 + h2 * x2 + h3 * x3;
        z   += (x0 + x1) + (x2 + x3);
        sv = nx;
    }
    float v = acc / (z + 1e-16f) + bias1[lane];
    v = (v > 0.f) ? v : expm1f(v);
    h1s[wid * D1 + lane] = v;
    __syncwarp();                          // own warp wrote all 32 values

    // gemm2 for this node: lane computes output cols (lane, lane+32)
    const float4* h4 = (const float4*)(h1s + wid * D1);
    float ox = 0.f, oy = 0.f;
#pragma unroll
    for (int k4 = 0; k4 < 8; k4++) {
        float4 h = h4[k4];
        float2 w0 = W2p[(k4 * 4 + 0) * 32 + lane];
        float2 w1 = W2p[(k4 * 4 + 1) * 32 + lane];
        float2 w2 = W2p[(k4 * 4 + 2) * 32 + lane];
        float2 w3 = W2p[(k4 * 4 + 3) * 32 + lane];
        ox += h.x * w0.x + h.y * w1.x + h.z * w2.x + h.w * w3.x;
        oy += h.x * w0.y + h.y * w1.y + h.z * w2.y + h.w * w3.y;
    }
    g_h2h[node * 32 + lane] = __floats2half2_rn(ox, oy);   // {col lane, col lane+32}

    float s = ox * as2[lane] + oy * as2[32 + lane];
    float d = ox * ad2[lane] + oy * ad2[32 + lane];
#pragma unroll
    for (int o = 16; o; o >>= 1) {
        s += __shfl_down_sync(0xffffffffu, s, o);
        d += __shfl_down_sync(0xffffffffu, d, o);
    }
    if (lane == 0) { g_s2[node] = s; g_d2[node] = d; }
}

// ---- gather layer 2 (warp / node; half2 = cols {lane, lane+32}) --------------
__global__ void k_gather2(const float* __restrict__ bias2, float* __restrict__ out) {
    int node = blockIdx.x * (blockDim.x >> 5) + (threadIdx.x >> 5);
    int lane = threadIdx.x & 31;
    if (node >= N_NODES) return;
    int beg = g_off[node];
    int n4  = (g_off[node + 1] - beg) >> 2;
    float dd = g_d2[node];
    float ax = 0.f, ay = 0.f, z = 0.f;

    const int4* ep = (const int4*)(g_esrc + beg);
    int4 sv = ep[0];
    for (int it = 0; it < n4; it++) {
        int4 nx = (it + 1 < n4) ? ep[it + 1] : sv;
        float l0 = g_s2[sv.x] + dd;
        float l1 = g_s2[sv.y] + dd;
        float l2 = g_s2[sv.z] + dd;
        float l3 = g_s2[sv.w] + dd;
        float2 h0 = __half22float2(g_h2h[sv.x * 32 + lane]);
        float2 h1 = __half22float2(g_h2h[sv.y * 32 + lane]);
        float2 h2 = __half22float2(g_h2h[sv.z * 32 + lane]);
        float2 h3 = __half22float2(g_h2h[sv.w * 32 + lane]);
        l0 = (l0 >= 0.f) ? l0 : SLOPE * l0;
        l1 = (l1 >= 0.f) ? l1 : SLOPE * l1;
        l2 = (l2 >= 0.f) ? l2 : SLOPE * l2;
        l3 = (l3 >= 0.f) ? l3 : SLOPE * l3;
        float x0 = __expf(l0), x1 = __expf(l1), x2 = __expf(l2), x3 = __expf(l3);
        ax += h0.x * x0 + h1.x * x1 + h2.x * x2 + h3.x * x3;
        ay += h0.y * x0 + h1.y * x1 + h2.y * x2 + h3.y * x3;
        z  += (x0 + x1) + (x2 + x3);
        sv = nx;
    }
    float inv = 1.f / (z + 1e-16f);
    out[node * D2 + lane]      = ax * inv + bias2[lane];
    out[node * D2 + 32 + lane] = ay * inv + bias2[32 + lane];
}

extern "C" void kernel_launch(void* const* d_in, const int* in_sizes, int n_in,
                              void* d_out, int out_size) {
    const float* x     = (const float*)d_in[0];
    const int*   ei32  = (const int*)d_in[1];
    const float* W1    = (const float*)d_in[2];
    const float* asrc1 = (const float*)d_in[3];
    const float* adst1 = (const float*)d_in[4];
    const float* bias1 = (const float*)d_in[5];
    const float* W2    = (const float*)d_in[6];
    const float* asrc2 = (const float*)d_in[7];
    const float* adst2 = (const float*)d_in[8];
    const float* bias2 = (const float*)d_in[9];
    float* out = (float*)d_out;

    const int T = 256;

    static cudaStream_t s2 = nullptr;
    static cudaEvent_t  evF = nullptr, evJ = nullptr;
    if (!s2) {
        cudaStreamCreateWithFlags(&s2, cudaStreamNonBlocking);
        cudaEventCreateWithFlags(&evF, cudaEventDisableTiming);
        cudaEventCreateWithFlags(&evJ, cudaEventDisableTiming);
    }

    cudaEventRecord(evF, 0);
    cudaStreamWaitEvent(s2, evF, 0);

    k_gemm1<<<((N_NODES / 4) * 8 + T - 1) / T, T, 0, s2>>>(x, W1, asrc1, adst1); // 1 (s2)
    cudaEventRecord(evJ, s2);
    k_hist<<<((ET + 3) / 4 + T - 1) / T, T>>>(ei32);                         // 2
    k_scanA<<<SCAN_BLKS, 256>>>();                                            // 3
    k_scanB<<<1, 256>>>();                                                    // 4 <- profiled
    k_scanC<<<SCAN_BLKS, 256>>>();                                            // 5
    k_scatter<<<((ET + 7) / 8 + T - 1) / T, T>>>(ei32);                       // 6

    cudaStreamWaitEvent(0, evJ, 0);
    k_layer1<<<N_NODES / 8, T>>>(bias1, W2, asrc2, adst2);                    // 7
    k_gather2<<<(N_NODES + 7) / 8, T>>>(bias2, out);                          // 8
}

// round 17
// speedup vs baseline: 2.3158x; 1.0150x over previous
#include <cuda_runtime.h>
#include <cuda_fp16.h>

#define N_NODES 50000
#define N_EDGES 800000
#define ET (N_EDGES + N_NODES)        // edges + self loops
#define ESRC_SZ (ET + 3 * N_NODES)    // padded CSR capacity
#define IN_DIM 128
#define D1 32
#define D2 64
#define SLOPE 0.2f
#define SENT N_NODES                  // sentinel node id
#define SCAN_BLKS ((N_NODES + 255) / 256)   // 196

// ---------------- scratch ----------------
__device__ __align__(16) __half  g_h1h[(N_NODES + 1) * D1];  // x@W1, fp16 (+sentinel=0)
__device__ float g_s1[(N_NODES + 1) * 2];                    // sentinel = -1e30
__device__ float g_d1[N_NODES * 2];
__device__ __align__(16) __half2 g_h2h[(N_NODES + 1) * 32];  // layer2 feats fp16, packed {c, c+32}
__device__ float g_s2[N_NODES + 1];                          // sentinel = -1e30
__device__ float g_d2[N_NODES];
__device__ int   g_deg[N_NODES];          // zero at load; re-zeroed by k_scanC each run
__device__ int   g_off[N_NODES + 1];
__device__ int   g_cur[N_NODES];
__device__ int   g_tmpoff[N_NODES];       // within-block exclusive prefix
__device__ int   g_bsum[SCAN_BLKS];       // per-block totals
__device__ __align__(16) int g_esrc[ESRC_SZ];                // CSR (pads sentinel-filled by scanC)

__device__ __forceinline__ int detect64(const int* ei32) {
    // int64 LE with values < 2^31 => odd 32-bit words are 0.
    return ((ei32[1] | ei32[3] | ei32[5] | ei32[7]) == 0) ? 1 : 0;
}

// ---------------- histogram of dst degrees (8 edges / thread) -----------------
__global__ void k_hist(const int* __restrict__ ei32) {
    int base = (blockIdx.x * blockDim.x + threadIdx.x) * 8;
    int is64 = detect64(ei32);
#pragma unroll
    for (int k = 0; k < 8; k++) {
        int i = base + k;
        if (i >= ET) return;
        int dst;
        if (i < N_EDGES) dst = is64 ? ei32[2 * (N_EDGES + i)] : ei32[N_EDGES + i];
        else             dst = i - N_EDGES;
        atomicAdd(&g_deg[dst], 1);
    }
}

// ---------------- scanA: block-local scan of padded degrees -------------------
__global__ void k_scanA() {
    __shared__ int sh[256];
    int i = blockIdx.x * 256 + threadIdx.x;
    int v = (i < N_NODES) ? ((g_deg[i] + 3) & ~3) : 0;
    int incl = v;
#pragma unroll
    for (int off = 1; off < 256; off <<= 1) {
        sh[threadIdx.x] = incl;
        __syncthreads();
        int add = (threadIdx.x >= off) ? sh[threadIdx.x - off] : 0;
        __syncthreads();
        incl += add;
    }
    if (i < N_NODES) g_tmpoff[i] = incl - v;
    if (threadIdx.x == 255) g_bsum[blockIdx.x] = incl;
}

// scanC: per-block prefix by reduction of bsum; offsets, pad fill, deg reset,
//        sentinel init, g_off[N]. (scanB absorbed.)
__global__ void k_scanC() {
    int t = threadIdx.x;
    // block prefix = sum of g_bsum[j] for j < blockIdx.x  (196 values max)
    int v = (t < blockIdx.x && t < SCAN_BLKS) ? g_bsum[t] : 0;
#pragma unroll
    for (int o = 16; o; o >>= 1) v += __shfl_down_sync(0xffffffffu, v, o);
    __shared__ int ws[8];
    if ((t & 31) == 0) ws[t >> 5] = v;
    __syncthreads();
    __shared__ int bp;
    if (t == 0) {
        int s = 0;
#pragma unroll
        for (int k = 0; k < 8; k++) s += ws[k];
        bp = s;
    }
    __syncthreads();

    int i = blockIdx.x * 256 + t;
    if (i < N_NODES) {
        int off = g_tmpoff[i] + bp;
        int d   = g_deg[i];
        g_off[i] = off;
        g_cur[i] = off;
        int pend = off + ((d + 3) & ~3);
        for (int p = off + d; p < pend; p++) g_esrc[p] = SENT;
        g_deg[i] = 0;
        if (i == N_NODES - 1) g_off[N_NODES] = pend;
    }
    if (blockIdx.x == 0) {
        if (t < D1) g_h1h[SENT * D1 + t] = __float2half(0.f);
        if (t < 32) g_h2h[SENT * 32 + t] = __floats2half2_rn(0.f, 0.f);
        if (t == 0) {
            g_s1[2 * SENT] = -1e30f;
            g_s1[2 * SENT + 1] = -1e30f;
            g_s2[SENT] = -1e30f;
        }
    }
}

// ---------------- scatter src indices into CSR buckets (8 / thread) -----------
__global__ void k_scatter(const int* __restrict__ ei32) {
    int base = (blockIdx.x * blockDim.x + threadIdx.x) * 8;
    int is64 = detect64(ei32);
#pragma unroll
    for (int k = 0; k < 8; k++) {
        int i = base + k;
        if (i >= ET) return;
        int src, dst;
        if (i < N_EDGES) {
            if (is64) { src = ei32[2 * i]; dst = ei32[2 * (N_EDGES + i)]; }
            else      { src = ei32[i];     dst = ei32[N_EDGES + i]; }
        } else {
            src = dst = i - N_EDGES;
        }
        int pos = atomicAdd(&g_cur[dst], 1);
        g_esrc[pos] = src;
    }
}

// ---------------- gemm1 + sd1 fused (8 threads / node QUAD, 4 cols x 4 nodes) --
__global__ void __launch_bounds__(256) k_gemm1(
        const float* __restrict__ x, const float* __restrict__ W1,
        const float* __restrict__ a_src, const float* __restrict__ a_dst) {
    __shared__ float4 Ws4[IN_DIM * (D1 / 4)];   // 16 KB
    for (int i = threadIdx.x; i < IN_DIM * (D1 / 4); i += blockDim.x)
        Ws4[i] = ((const float4*)W1)[i];
    __syncthreads();

    int tid  = blockIdx.x * blockDim.x + threadIdx.x;
    int quad = tid >> 3;
    int sub  = tid & 7;
    if (quad >= N_NODES / 4) return;   // 50000 % 4 == 0
    int n0 = quad * 4;

    const float4* x0p = (const float4*)(x + (n0 + 0) * IN_DIM);
    const float4* x1p = (const float4*)(x + (n0 + 1) * IN_DIM);
    const float4* x2p = (const float4*)(x + (n0 + 2) * IN_DIM);
    const float4* x3p = (const float4*)(x + (n0 + 3) * IN_DIM);
    float4 a0 = make_float4(0.f, 0.f, 0.f, 0.f);
    float4 a1 = a0, a2 = a0, a3 = a0;
#pragma unroll 2
    for (int k4 = 0; k4 < 32; k4++) {
        float4 w0 = Ws4[(k4 * 4 + 0) * 8 + sub];
        float4 w1 = Ws4[(k4 * 4 + 1) * 8 + sub];
        float4 w2 = Ws4[(k4 * 4 + 2) * 8 + sub];
        float4 w3 = Ws4[(k4 * 4 + 3) * 8 + sub];
        float4 xv;
        xv = x0p[k4];
        a0.x += xv.x * w0.x + xv.y * w1.x + xv.z * w2.x + xv.w * w3.x;
        a0.y += xv.x * w0.y + xv.y * w1.y + xv.z * w2.y + xv.w * w3.y;
        a0.z += xv.x * w0.z + xv.y * w1.z + xv.z * w2.z + xv.w * w3.z;
        a0.w += xv.x * w0.w + xv.y * w1.w + xv.z * w2.w + xv.w * w3.w;
        xv = x1p[k4];
        a1.x += xv.x * w0.x + xv.y * w1.x + xv.z * w2.x + xv.w * w3.x;
        a1.y += xv.x * w0.y + xv.y * w1.y + xv.z * w2.y + xv.w * w3.y;
        a1.z += xv.x * w0.z + xv.y * w1.z + xv.z * w2.z + xv.w * w3.z;
        a1.w += xv.x * w0.w + xv.y * w1.w + xv.z * w2.w + xv.w * w3.w;
        xv = x2p[k4];
        a2.x += xv.x * w0.x + xv.y * w1.x + xv.z * w2.x + xv.w * w3.x;
        a2.y += xv.x * w0.y + xv.y * w1.y + xv.z * w2.y + xv.w * w3.y;
        a2.z += xv.x * w0.z + xv.y * w1.z + xv.z * w2.z + xv.w * w3.z;
        a2.w += xv.x * w0.w + xv.y * w1.w + xv.z * w2.w + xv.w * w3.w;
        xv = x3p[k4];
        a3.x += xv.x * w0.x + xv.y * w1.x + xv.z * w2.x + xv.w * w3.x;
        a3.y += xv.x * w0.y + xv.y * w1.y + xv.z * w2.y + xv.w * w3.y;
        a3.z += xv.x * w0.z + xv.y * w1.z + xv.z * w2.z + xv.w * w3.z;
        a3.w += xv.x * w0.w + xv.y * w1.w + xv.z * w2.w + xv.w * w3.w;
    }
    __half2* h1p = (__half2*)g_h1h;
    h1p[(n0 + 0) * 16 + sub * 2]     = __floats2half2_rn(a0.x, a0.y);
    h1p[(n0 + 0) * 16 + sub * 2 + 1] = __floats2half2_rn(a0.z, a0.w);
    h1p[(n0 + 1) * 16 + sub * 2]     = __floats2half2_rn(a1.x, a1.y);
    h1p[(n0 + 1) * 16 + sub * 2 + 1] = __floats2half2_rn(a1.z, a1.w);
    h1p[(n0 + 2) * 16 + sub * 2]     = __floats2half2_rn(a2.x, a2.y);
    h1p[(n0 + 2) * 16 + sub * 2 + 1] = __floats2half2_rn(a2.z, a2.w);
    h1p[(n0 + 3) * 16 + sub * 2]     = __floats2half2_rn(a3.x, a3.y);
    h1p[(n0 + 3) * 16 + sub * 2 + 1] = __floats2half2_rn(a3.z, a3.w);

    float4 as = ((const float4*)a_src)[sub];
    float4 ad = ((const float4*)a_dst)[sub];
    float s0 = a0.x * as.x + a0.y * as.y + a0.z * as.z + a0.w * as.w;
    float d0 = a0.x * ad.x + a0.y * ad.y + a0.z * ad.z + a0.w * ad.w;
    float s1 = a1.x * as.x + a1.y * as.y + a1.z * as.z + a1.w * as.w;
    float d1 = a1.x * ad.x + a1.y * ad.y + a1.z * ad.z + a1.w * ad.w;
    float s2 = a2.x * as.x + a2.y * as.y + a2.z * as.z + a2.w * as.w;
    float d2 = a2.x * ad.x + a2.y * ad.y + a2.z * ad.z + a2.w * ad.w;
    float s3 = a3.x * as.x + a3.y * as.y + a3.z * as.z + a3.w * as.w;
    float d3 = a3.x * ad.x + a3.y * ad.y + a3.z * ad.z + a3.w * ad.w;
#pragma unroll
    for (int o = 2; o; o >>= 1) {
        s0 += __shfl_down_sync(0xffffffffu, s0, o, 4);
        d0 += __shfl_down_sync(0xffffffffu, d0, o, 4);
        s1 += __shfl_down_sync(0xffffffffu, s1, o, 4);
        d1 += __shfl_down_sync(0xffffffffu, d1, o, 4);
        s2 += __shfl_down_sync(0xffffffffu, s2, o, 4);
        d2 += __shfl_down_sync(0xffffffffu, d2, o, 4);
        s3 += __shfl_down_sync(0xffffffffu, s3, o, 4);
        d3 += __shfl_down_sync(0xffffffffu, d3, o, 4);
    }
    if ((sub & 3) == 0) {
        int head = sub >> 2;
        g_s1[(n0 + 0) * 2 + head] = s0;  g_d1[(n0 + 0) * 2 + head] = d0;
        g_s1[(n0 + 1) * 2 + head] = s1;  g_d1[(n0 + 1) * 2 + head] = d1;
        g_s1[(n0 + 2) * 2 + head] = s2;  g_d1[(n0 + 2) * 2 + head] = d2;
        g_s1[(n0 + 3) * 2 + head] = s3;  g_d1[(n0 + 3) * 2 + head] = d3;
    }
}

// ---- layer1 fused: gather+elu (warp/node) then block-local gemm2+sd2 ---------
// Grid is exact: 6250 blocks x 8 warps = 50000 nodes. No early returns.
__global__ void __launch_bounds__(256) k_layer1(
        const float* __restrict__ bias1, const float* __restrict__ W2,
        const float* __restrict__ as2, const float* __restrict__ ad2) {
    __shared__ float  h1s[8 * D1];        // 1 KB
    __shared__ float2 W2p[D1 * 32];       // 8 KB: W2 packed {col c, col c+32} per k

    for (int i = threadIdx.x; i < D1 * 32; i += 256) {
        int k = i >> 5, c = i & 31;
        W2p[i] = make_float2(W2[k * D2 + c], W2[k * D2 + 32 + c]);
    }
    __syncthreads();

    int wid  = threadIdx.x >> 5;
    int lane = threadIdx.x & 31;
    int node = blockIdx.x * 8 + wid;
    int beg = g_off[node];
    int n4  = (g_off[node + 1] - beg) >> 2;   // >= 1
    int head = lane >> 4;
    float dd = g_d1[node * 2 + head];
    float acc = 0.f, z = 0.f;

    const int4* ep = (const int4*)(g_esrc + beg);
    int4 sv = ep[0];
    for (int it = 0; it < n4; it++) {
        int4 nx = (it + 1 < n4) ? ep[it + 1] : sv;
        float l0 = g_s1[sv.x * 2 + head] + dd;
        float l1 = g_s1[sv.y * 2 + head] + dd;
        float l2 = g_s1[sv.z * 2 + head] + dd;
        float l3 = g_s1[sv.w * 2 + head] + dd;
        float h0 = __half2float(g_h1h[sv.x * D1 + lane]);
        float h1 = __half2float(g_h1h[sv.y * D1 + lane]);
        float h2 = __half2float(g_h1h[sv.z * D1 + lane]);
        float h3 = __half2float(g_h1h[sv.w * D1 + lane]);
        l0 = (l0 >= 0.f) ? l0 : SLOPE * l0;
        l1 = (l1 >= 0.f) ? l1 : SLOPE * l1;
        l2 = (l2 >= 0.f) ? l2 : SLOPE * l2;
        l3 = (l3 >= 0.f) ? l3 : SLOPE * l3;
        float x0 = __expf(l0), x1 = __expf(l1), x2 = __expf(l2), x3 = __expf(l3);
        acc += h0 * x0 + h1 * x1 + h2 * x2 + h3 * x3;
        z   += (x0 + x1) + (x2 + x3);
        sv = nx;
    }
    float v = acc / (z + 1e-16f) + bias1[lane];
    v = (v > 0.f) ? v : expm1f(v);
    h1s[wid * D1 + lane] = v;
    __syncwarp();

    // gemm2 for this node: lane computes output cols (lane, lane+32)
    const float4* h4 = (const float4*)(h1s + wid * D1);
    float ox = 0.f, oy = 0.f;
#pragma unroll
    for (int k4 = 0; k4 < 8; k4++) {
        float4 h = h4[k4];
        float2 w0 = W2p[(k4 * 4 + 0) * 32 + lane];
        float2 w1 = W2p[(k4 * 4 + 1) * 32 + lane];
        float2 w2 = W2p[(k4 * 4 + 2) * 32 + lane];
        float2 w3 = W2p[(k4 * 4 + 3) * 32 + lane];
        ox += h.x * w0.x + h.y * w1.x + h.z * w2.x + h.w * w3.x;
        oy += h.x * w0.y + h.y * w1.y + h.z * w2.y + h.w * w3.y;
    }
    g_h2h[node * 32 + lane] = __floats2half2_rn(ox, oy);   // {col lane, col lane+32}

    float s = ox * as2[lane] + oy * as2[32 + lane];
    float d = ox * ad2[lane] + oy * ad2[32 + lane];
#pragma unroll
    for (int o = 16; o; o >>= 1) {
        s += __shfl_down_sync(0xffffffffu, s, o);
        d += __shfl_down_sync(0xffffffffu, d, o);
    }
    if (lane == 0) { g_s2[node] = s; g_d2[node] = d; }
}

// ---- gather layer 2 (warp / node; half2 = cols {lane, lane+32}) --------------
__global__ void k_gather2(const float* __restrict__ bias2, float* __restrict__ out) {
    int node = blockIdx.x * (blockDim.x >> 5) + (threadIdx.x >> 5);
    int lane = threadIdx.x & 31;
    if (node >= N_NODES) return;
    int beg = g_off[node];
    int n4  = (g_off[node + 1] - beg) >> 2;
    float dd = g_d2[node];
    float ax = 0.f, ay = 0.f, z = 0.f;

    const int4* ep = (const int4*)(g_esrc + beg);
    int4 sv = ep[0];
    for (int it = 0; it < n4; it++) {
        int4 nx = (it + 1 < n4) ? ep[it + 1] : sv;
        float l0 = g_s2[sv.x] + dd;
        float l1 = g_s2[sv.y] + dd;
        float l2 = g_s2[sv.z] + dd;
        float l3 = g_s2[sv.w] + dd;
        float2 h0 = __half22float2(g_h2h[sv.x * 32 + lane]);
        float2 h1 = __half22float2(g_h2h[sv.y * 32 + lane]);
        float2 h2 = __half22float2(g_h2h[sv.z * 32 + lane]);
        float2 h3 = __half22float2(g_h2h[sv.w * 32 + lane]);
        l0 = (l0 >= 0.f) ? l0 : SLOPE * l0;
        l1 = (l1 >= 0.f) ? l1 : SLOPE * l1;
        l2 = (l2 >= 0.f) ? l2 : SLOPE * l2;
        l3 = (l3 >= 0.f) ? l3 : SLOPE * l3;
        float x0 = __expf(l0), x1 = __expf(l1), x2 = __expf(l2), x3 = __expf(l3);
        ax += h0.x * x0 + h1.x * x1 + h2.x * x2 + h3.x * x3;
        ay += h0.y * x0 + h1.y * x1 + h2.y * x2 + h3.y * x3;
        z  += (x0 + x1) + (x2 + x3);
        sv = nx;
    }
    float inv = 1.f / (z + 1e-16f);
    out[node * D2 + lane]      = ax * inv + bias2[lane];
    out[node * D2 + 32 + lane] = ay * inv + bias2[32 + lane];
}

extern "C" void kernel_launch(void* const* d_in, const int* in_sizes, int n_in,
                              void* d_out, int out_size) {
    const float* x     = (const float*)d_in[0];
    const int*   ei32  = (const int*)d_in[1];
    const float* W1    = (const float*)d_in[2];
    const float* asrc1 = (const float*)d_in[3];
    const float* adst1 = (const float*)d_in[4];
    const float* bias1 = (const float*)d_in[5];
    const float* W2    = (const float*)d_in[6];
    const float* asrc2 = (const float*)d_in[7];
    const float* adst2 = (const float*)d_in[8];
    const float* bias2 = (const float*)d_in[9];
    float* out = (float*)d_out;

    const int T = 256;

    static cudaStream_t s2 = nullptr;
    static cudaEvent_t  evF = nullptr, evJ = nullptr;
    if (!s2) {
        cudaStreamCreateWithFlags(&s2, cudaStreamNonBlocking);
        cudaEventCreateWithFlags(&evF, cudaEventDisableTiming);
        cudaEventCreateWithFlags(&evJ, cudaEventDisableTiming);
    }

    cudaEventRecord(evF, 0);
    cudaStreamWaitEvent(s2, evF, 0);

    k_gemm1<<<((N_NODES / 4) * 8 + T - 1) / T, T, 0, s2>>>(x, W1, asrc1, adst1); // 1 (s2)
    cudaEventRecord(evJ, s2);
    k_hist<<<((ET + 7) / 8 + T - 1) / T, T>>>(ei32);                         // 2
    k_scanA<<<SCAN_BLKS, 256>>>();                                            // 3
    k_scanC<<<SCAN_BLKS, 256>>>();                                            // 4 <- profiled
    k_scatter<<<((ET + 7) / 8 + T - 1) / T, T>>>(ei32);                       // 5

    cudaStreamWaitEvent(0, evJ, 0);
    k_layer1<<<N_NODES / 8, T>>>(bias1, W2, asrc2, adst2);                    // 6
    k_gather2<<<(N_NODES + 7) / 8, T>>>(bias2, out);                          // 7
}